// round 3
// baseline (speedup 1.0000x reference)
#include <cuda_runtime.h>
#include <math.h>

// Problem constants: N=8, R=256, IN=64, OUT=64, MODE=32
// kx mode list (64 entries): k<32 -> kx=k ; k>=32 -> kx=192+k (224..255)

// ---------------- device scratch ----------------
__device__ float g_T1[128 * 256];             // fwd h-DFT:  [kxc=2k+p][h]
__device__ float g_T2[64 * 512];              // fwd w-DFT:  [kyp=2ky+p][w | 256+w]
__device__ float g_T4[512 * 128];             // inv h-DFT:  [hp=2h+p][kxp=2k+p]
__device__ float g_T5[256 * 64];              // inv w-DFT:  [w][kyp]
__device__ float g_X1[(size_t)8 * 128 * 256 * 64];  // [n][kxc][w][i]   (67MB)
__device__ float g_X2[(size_t)8 * 64 * 64 * 64];    // [n][kx][kyp][i]  (8.4MB)
__device__ float g_F [(size_t)8 * 128 * 32 * 64];   // [n][kxp][ky][o]  (8.4MB)
__device__ float g_G [(size_t)8 * 512 * 2048];      // [n][hp][ky*64+o] (33.5MB)

__device__ __forceinline__ float silu_f(float t) {
    return t / (1.0f + __expf(-t));
}

// ---------------- twiddle init (runs every launch; deterministic) ----------------
__global__ void k_init() {
    int t = blockIdx.x * blockDim.x + threadIdx.x;   // 16384 threads
    {
        // T1: e^{-i 2pi kx h / 256}: row 2k = cos, row 2k+1 = -sin
        int k = t >> 8, h = t & 255;
        int kx = (k < 32) ? k : 192 + k;
        float s, c;
        sincospif((float)((kx * h) & 255) * (1.0f / 128.0f), &s, &c);
        g_T1[(2 * k) * 256 + h]     = c;
        g_T1[(2 * k + 1) * 256 + h] = -s;
    }
    if (t < 8192) {
        // T2: X2re = sum (X1re*c + X1im*s); X2im = sum (X1im*c - X1re*s)
        int ky = t >> 8, w = t & 255;
        float s, c;
        sincospif((float)((ky * w) & 255) * (1.0f / 128.0f), &s, &c);
        g_T2[(2 * ky) * 512 + w]           = c;
        g_T2[(2 * ky) * 512 + 256 + w]     = s;
        g_T2[(2 * ky + 1) * 512 + w]       = -s;
        g_T2[(2 * ky + 1) * 512 + 256 + w] = c;
    }
    {
        // T4: e^{+i 2pi kx h/256}: Gre = Fre*c - Fim*s ; Gim = Fre*s + Fim*c
        int h = t >> 6, k = t & 63;
        int kx = (k < 32) ? k : 192 + k;
        float s, c;
        sincospif((float)((kx * h) & 255) * (1.0f / 128.0f), &s, &c);
        g_T4[(2 * h) * 128 + 2 * k]         = c;
        g_T4[(2 * h) * 128 + 2 * k + 1]     = -s;
        g_T4[(2 * h + 1) * 128 + 2 * k]     = s;
        g_T4[(2 * h + 1) * 128 + 2 * k + 1] = c;
    }
    if (t < 8192) {
        // T5: y[w] = sum_ky c_ky * (Gre*cos - Gim*sin), c_0=1 else 2
        int w = t >> 5, ky = t & 31;
        float s, c;
        sincospif((float)((ky * w) & 255) * (1.0f / 128.0f), &s, &c);
        float f = (ky == 0) ? 1.0f : 2.0f;
        g_T5[w * 64 + 2 * ky]     = f * c;
        g_T5[w * 64 + 2 * ky + 1] = -f * s;
    }
}

// ---------------- residual: d_out = x @ res_w + res_b ----------------
// block: 256 pixels x 64 outs, 256 threads, 8x8 register tile. dynamic smem.
__global__ void __launch_bounds__(256) k_resid(const float* __restrict__ x,
                                               const float* __restrict__ rw,
                                               const float* __restrict__ rb,
                                               float* __restrict__ out) {
    extern __shared__ float sm[];
    float(*As)[260] = (float(*)[260])sm;            // [64 k][256 m(+pad)]
    float(*Bs)[68]  = (float(*)[68])(sm + 64 * 260); // [64 k][64 o(+pad)]
    float* bb = sm + 64 * 260 + 64 * 68;
    int tid = threadIdx.x;
    const float* xb = x + (size_t)blockIdx.x * 16384;
#pragma unroll
    for (int q = 0; q < 16; q++) {
        int f4 = tid + q * 256;
        int m = f4 >> 4, j = f4 & 15;
        float4 v = *(const float4*)(xb + m * 64 + j * 4);
        As[j * 4 + 0][m] = v.x; As[j * 4 + 1][m] = v.y;
        As[j * 4 + 2][m] = v.z; As[j * 4 + 3][m] = v.w;
    }
#pragma unroll
    for (int q = 0; q < 4; q++) {
        int f4 = tid + q * 256;
        int k = f4 >> 4, j = f4 & 15;
        *(float4*)&Bs[k][j * 4] = *(const float4*)(rw + k * 64 + j * 4);
    }
    if (tid < 64) bb[tid] = rb[tid];
    __syncthreads();
    int r0 = (tid >> 3) * 8, c0 = (tid & 7) * 8;
    float acc[8][8];
#pragma unroll
    for (int i = 0; i < 8; i++)
#pragma unroll
        for (int j = 0; j < 8; j++) acc[i][j] = bb[c0 + j];
#pragma unroll 4
    for (int k = 0; k < 64; k++) {
        float a[8], b[8];
        *(float4*)(a)     = *(float4*)&As[k][r0];
        *(float4*)(a + 4) = *(float4*)&As[k][r0 + 4];
        *(float4*)(b)     = *(float4*)&Bs[k][c0];
        *(float4*)(b + 4) = *(float4*)&Bs[k][c0 + 4];
#pragma unroll
        for (int i = 0; i < 8; i++)
#pragma unroll
            for (int j = 0; j < 8; j++) acc[i][j] += a[i] * b[j];
    }
    float* ob = out + (size_t)blockIdx.x * 16384;
#pragma unroll
    for (int i = 0; i < 8; i++) {
        int m = r0 + i;
        *(float4*)(ob + m * 64 + c0)     = make_float4(acc[i][0], acc[i][1], acc[i][2], acc[i][3]);
        *(float4*)(ob + m * 64 + c0 + 4) = make_float4(acc[i][4], acc[i][5], acc[i][6], acc[i][7]);
    }
}

// ---------------- S1: X1[n][kxc][w*64+i] = T1 @ x[n]  (M=128,K=256,N=16384) ----------------
__global__ void __launch_bounds__(256) k_s1(const float* __restrict__ x) {
    __shared__ float As[16][132];   // [kk][m=kxc]
    __shared__ float Bs[16][128];   // [kk][col]
    int tid = threadIdx.x;
    int n = blockIdx.y;
    int colbase = blockIdx.x * 128;
    const float* B = x + (size_t)n * (256 * 16384);
    float acc[8][8] = {};
    int r0 = (tid >> 4) * 8, c0 = (tid & 15) * 8;
    for (int kc = 0; kc < 256; kc += 16) {
#pragma unroll
        for (int q = 0; q < 2; q++) {
            int f4 = tid + q * 256;
            int m = f4 >> 2, j = f4 & 3;
            float4 v = *(const float4*)(g_T1 + m * 256 + kc + j * 4);
            As[j * 4 + 0][m] = v.x; As[j * 4 + 1][m] = v.y;
            As[j * 4 + 2][m] = v.z; As[j * 4 + 3][m] = v.w;
        }
#pragma unroll
        for (int q = 0; q < 2; q++) {
            int f4 = tid + q * 256;
            int kk = f4 >> 5, c4 = f4 & 31;
            *(float4*)&Bs[kk][c4 * 4] =
                *(const float4*)(B + (size_t)(kc + kk) * 16384 + colbase + c4 * 4);
        }
        __syncthreads();
#pragma unroll 4
        for (int k = 0; k < 16; k++) {
            float a[8], b[8];
            *(float4*)(a)     = *(float4*)&As[k][r0];
            *(float4*)(a + 4) = *(float4*)&As[k][r0 + 4];
            *(float4*)(b)     = *(float4*)&Bs[k][c0];
            *(float4*)(b + 4) = *(float4*)&Bs[k][c0 + 4];
#pragma unroll
            for (int i = 0; i < 8; i++)
#pragma unroll
                for (int j = 0; j < 8; j++) acc[i][j] += a[i] * b[j];
        }
        __syncthreads();
    }
    float* C = g_X1 + (size_t)n * 128 * 16384 + colbase;
#pragma unroll
    for (int i = 0; i < 8; i++) {
        int row = r0 + i;
        *(float4*)(C + (size_t)row * 16384 + c0)     = make_float4(acc[i][0], acc[i][1], acc[i][2], acc[i][3]);
        *(float4*)(C + (size_t)row * 16384 + c0 + 4) = make_float4(acc[i][4], acc[i][5], acc[i][6], acc[i][7]);
    }
}

// ---------------- S2: per (n,kx): X2[kyp][i] = T2[64][512] @ X1panel[512][64] ----------------
__global__ void __launch_bounds__(64) k_s2() {
    __shared__ float As[16][68];    // [kk][kyp]
    __shared__ float Bs[16][64];    // [kk][i]
    int tid = threadIdx.x;
    int kx = blockIdx.x & 63, n = blockIdx.x >> 6;
    const float* B = g_X1 + (size_t)(n * 128 + 2 * kx) * 16384;  // [512][64] contiguous
    float acc[8][8] = {};
    int r0 = (tid >> 3) * 8, c0 = (tid & 7) * 8;
    for (int kc = 0; kc < 512; kc += 16) {
#pragma unroll
        for (int q = 0; q < 4; q++) {
            int f4 = tid + q * 64;       // 256 = 64m * 4j
            int m = f4 >> 2, j = f4 & 3;
            float4 v = *(const float4*)(g_T2 + m * 512 + kc + j * 4);
            As[j * 4 + 0][m] = v.x; As[j * 4 + 1][m] = v.y;
            As[j * 4 + 2][m] = v.z; As[j * 4 + 3][m] = v.w;
        }
#pragma unroll
        for (int q = 0; q < 4; q++) {
            int f4 = tid + q * 64;       // 256 f4 = 1024 floats contiguous
            *(float4*)&Bs[0][f4 * 4] = *(const float4*)(B + kc * 64 + f4 * 4);
        }
        __syncthreads();
#pragma unroll 4
        for (int k = 0; k < 16; k++) {
            float a[8], b[8];
            *(float4*)(a)     = *(float4*)&As[k][r0];
            *(float4*)(a + 4) = *(float4*)&As[k][r0 + 4];
            *(float4*)(b)     = *(float4*)&Bs[k][c0];
            *(float4*)(b + 4) = *(float4*)&Bs[k][c0 + 4];
#pragma unroll
            for (int i = 0; i < 8; i++)
#pragma unroll
                for (int j = 0; j < 8; j++) acc[i][j] += a[i] * b[j];
        }
        __syncthreads();
    }
    float* C = g_X2 + (size_t)(n * 64 + kx) * 4096;  // [kyp][i]
#pragma unroll
    for (int i = 0; i < 8; i++) {
        *(float4*)(C + (r0 + i) * 64 + c0)     = make_float4(acc[i][0], acc[i][1], acc[i][2], acc[i][3]);
        *(float4*)(C + (r0 + i) * 64 + c0 + 4) = make_float4(acc[i][4], acc[i][5], acc[i][6], acc[i][7]);
    }
}

// ---------------- S3: mode channel mix (complex), scale by 1/65536 ----------------
__global__ void __launch_bounds__(256) k_s3(const float* __restrict__ w0,
                                            const float* __restrict__ w1) {
    __shared__ float Wre[64][64], Wim[64][64];
    __shared__ float Xre[8][64], Xim[8][64];
    int tid = threadIdx.x;
    int ky = blockIdx.x & 31, k = blockIdx.x >> 5;
    const float* W = (k < 32) ? (w0 + (size_t)(k * 32 + ky) * 4096 * 2)
                              : (w1 + (size_t)((k - 32) * 32 + ky) * 4096 * 2);
#pragma unroll
    for (int q = 0; q < 16; q++) {
        int e = tid + q * 256;          // i*64+o
        float2 v = *(const float2*)(W + (size_t)e * 2);
        Wre[e >> 6][e & 63] = v.x;
        Wim[e >> 6][e & 63] = v.y;
    }
#pragma unroll
    for (int q = 0; q < 2; q++) {
        int e = tid + q * 256;          // n*64+i
        int n = e >> 6, i = e & 63;
        Xre[n][i] = g_X2[((size_t)(n * 64 + k) * 64 + 2 * ky) * 64 + i];
        Xim[n][i] = g_X2[((size_t)(n * 64 + k) * 64 + 2 * ky + 1) * 64 + i];
    }
    __syncthreads();
    const float sc = 1.0f / 65536.0f;   // fwd ortho 1/256 * inv ortho 1/256
#pragma unroll
    for (int q = 0; q < 2; q++) {
        int e = tid + q * 256;
        int n = e >> 6, o = e & 63;
        float fre = 0.0f, fim = 0.0f;
#pragma unroll 8
        for (int i = 0; i < 64; i++) {
            float xr = Xre[n][i], xi = Xim[n][i];
            float wr = Wre[i][o], wi = Wim[i][o];
            fre += xr * wr - xi * wi;
            fim += xr * wi + xi * wr;
        }
        g_F[((size_t)(n * 128 + 2 * k) * 32 + ky) * 64 + o]     = fre * sc;
        g_F[((size_t)(n * 128 + 2 * k + 1) * 32 + ky) * 64 + o] = fim * sc;
    }
}

// ---------------- S4: per n: G[512 hp][2048] = T4[512][128] @ F[n][128][2048] ----------------
__global__ void __launch_bounds__(256) k_s4() {
    __shared__ float As[16][132];
    __shared__ float Bs[16][128];
    int tid = threadIdx.x;
    int colbase = blockIdx.x * 128;
    int m0 = blockIdx.y * 128;
    int n = blockIdx.z;
    const float* B = g_F + (size_t)n * 128 * 2048;
    float acc[8][8] = {};
    int r0 = (tid >> 4) * 8, c0 = (tid & 15) * 8;
    for (int kc = 0; kc < 128; kc += 16) {
#pragma unroll
        for (int q = 0; q < 2; q++) {
            int f4 = tid + q * 256;
            int m = f4 >> 2, j = f4 & 3;
            float4 v = *(const float4*)(g_T4 + (size_t)(m0 + m) * 128 + kc + j * 4);
            As[j * 4 + 0][m] = v.x; As[j * 4 + 1][m] = v.y;
            As[j * 4 + 2][m] = v.z; As[j * 4 + 3][m] = v.w;
        }
#pragma unroll
        for (int q = 0; q < 2; q++) {
            int f4 = tid + q * 256;
            int kk = f4 >> 5, c4 = f4 & 31;
            *(float4*)&Bs[kk][c4 * 4] =
                *(const float4*)(B + (size_t)(kc + kk) * 2048 + colbase + c4 * 4);
        }
        __syncthreads();
#pragma unroll 4
        for (int k = 0; k < 16; k++) {
            float a[8], b[8];
            *(float4*)(a)     = *(float4*)&As[k][r0];
            *(float4*)(a + 4) = *(float4*)&As[k][r0 + 4];
            *(float4*)(b)     = *(float4*)&Bs[k][c0];
            *(float4*)(b + 4) = *(float4*)&Bs[k][c0 + 4];
#pragma unroll
            for (int i = 0; i < 8; i++)
#pragma unroll
                for (int j = 0; j < 8; j++) acc[i][j] += a[i] * b[j];
        }
        __syncthreads();
    }
    float* C = g_G + (size_t)n * 512 * 2048 + colbase;
#pragma unroll
    for (int i = 0; i < 8; i++) {
        int row = m0 + r0 + i;
        *(float4*)(C + (size_t)row * 2048 + c0)     = make_float4(acc[i][0], acc[i][1], acc[i][2], acc[i][3]);
        *(float4*)(C + (size_t)row * 2048 + c0 + 4) = make_float4(acc[i][4], acc[i][5], acc[i][6], acc[i][7]);
    }
}

// ---------------- S5: per (n,h): y[w][o] = T5[256][64] @ G[64 kyp][64 o], + res, silu ----------------
__global__ void __launch_bounds__(256) k_s5(float* __restrict__ out) {
    extern __shared__ float sm[];
    float(*As)[260] = (float(*)[260])sm;             // [64 kyp][256 w(+pad)]
    float(*Bs)[68]  = (float(*)[68])(sm + 64 * 260);  // [64 kyp][64 o(+pad)]
    int tid = threadIdx.x;
    int h = blockIdx.x & 255, n = blockIdx.x >> 8;
#pragma unroll
    for (int q = 0; q < 16; q++) {
        int f4 = tid + q * 256;          // 4096 f4s of T5 (transpose load)
        int w = f4 >> 4, j = f4 & 15;
        float4 v = *(const float4*)(g_T5 + w * 64 + j * 4);
        As[j * 4 + 0][w] = v.x; As[j * 4 + 1][w] = v.y;
        As[j * 4 + 2][w] = v.z; As[j * 4 + 3][w] = v.w;
    }
    const float* G = g_G + (size_t)(n * 256 + h) * 4096;  // [p][ky][o]
#pragma unroll
    for (int q = 0; q < 4; q++) {
        int e4 = tid + q * 256;          // 1024 f4s
        int p = e4 >> 9, ky = (e4 >> 4) & 31, j = e4 & 15;
        float4 v = *(const float4*)(G + p * 2048 + ky * 64 + j * 4);
        *(float4*)&Bs[2 * ky + p][j * 4] = v;
    }
    __syncthreads();
    int r0 = (tid >> 3) * 8, c0 = (tid & 7) * 8;
    float acc[8][8] = {};
#pragma unroll 4
    for (int k = 0; k < 64; k++) {
        float a[8], b[8];
        *(float4*)(a)     = *(float4*)&As[k][r0];
        *(float4*)(a + 4) = *(float4*)&As[k][r0 + 4];
        *(float4*)(b)     = *(float4*)&Bs[k][c0];
        *(float4*)(b + 4) = *(float4*)&Bs[k][c0 + 4];
#pragma unroll
        for (int i = 0; i < 8; i++)
#pragma unroll
            for (int j = 0; j < 8; j++) acc[i][j] += a[i] * b[j];
    }
    float* ob = out + (size_t)(n * 256 + h) * 16384;   // [w][o], currently holds residual
#pragma unroll
    for (int i = 0; i < 8; i++) {
        int w = r0 + i;
        float4 rv0 = *(float4*)(ob + w * 64 + c0);
        float4 rv1 = *(float4*)(ob + w * 64 + c0 + 4);
        float4 o0, o1;
        o0.x = silu_f(acc[i][0] + rv0.x); o0.y = silu_f(acc[i][1] + rv0.y);
        o0.z = silu_f(acc[i][2] + rv0.z); o0.w = silu_f(acc[i][3] + rv0.w);
        o1.x = silu_f(acc[i][4] + rv1.x); o1.y = silu_f(acc[i][5] + rv1.y);
        o1.z = silu_f(acc[i][6] + rv1.z); o1.w = silu_f(acc[i][7] + rv1.w);
        *(float4*)(ob + w * 64 + c0)     = o0;
        *(float4*)(ob + w * 64 + c0 + 4) = o1;
    }
}

// ---------------- launch ----------------
extern "C" void kernel_launch(void* const* d_in, const int* in_sizes, int n_in,
                              void* d_out, int out_size) {
    const float* x  = (const float*)d_in[0];
    const float* w0 = (const float*)d_in[1];
    const float* w1 = (const float*)d_in[2];
    const float* rw = (const float*)d_in[3];
    const float* rb = (const float*)d_in[4];
    float* out = (float*)d_out;

    const int SMEM_BIG = (64 * 260 + 64 * 68 + 64) * 4;   // 84224 bytes
    cudaFuncSetAttribute(k_resid, cudaFuncAttributeMaxDynamicSharedMemorySize, SMEM_BIG);
    cudaFuncSetAttribute(k_s5,    cudaFuncAttributeMaxDynamicSharedMemorySize, SMEM_BIG);

    k_init<<<64, 256>>>();
    k_resid<<<2048, 256, SMEM_BIG>>>(x, rw, rb, out);
    dim3 g1(128, 8);
    k_s1<<<g1, 256>>>(x);
    k_s2<<<512, 64>>>();
    k_s3<<<2048, 256>>>(w0, w1);
    dim3 g4(16, 4, 8);
    k_s4<<<g4, 256>>>();
    k_s5<<<2048, 256, SMEM_BIG>>>(out);
}

// round 7
// speedup vs baseline: 1.2780x; 1.2780x over previous
#include <cuda_runtime.h>
#include <math.h>

// Problem constants: N=8, R=256, IN=64, OUT=64, MODE=32
// kx mode list (64): k<32 -> kx=k ; k>=32 -> kx=192+k

// ---------------- device scratch ----------------
__device__ float g_T2aT[256 * 64];    // fwd w-DFT, transposed: [w][r=p*32+ky]
__device__ float g_T1T[256 * 128];    // fwd h-DFT cos/sin, transposed: [h][m] m<64:cos m>=64:sin
__device__ float g_T4T[128 * 512];    // inv h-DFT, transposed: [kxp][hp]
__device__ float g_T5t[64 * 256];     // inv w-DFT, transposed: [kyp][w]
__device__ float g_Xw[(size_t)8 * 256 * 4096];  // [n][h][p*2048+ky*64+i]  (33.5MB)
__device__ float g_C [(size_t)8 * 128 * 4096];  // [n][m(cos|sin)][p*2048+ky*64+i] (16.8MB)
__device__ float g_F [(size_t)8 * 128 * 32 * 64]; // [n][kxp][ky][o] (8.4MB)
__device__ float g_G [(size_t)8 * 512 * 2048];    // [n][hp][ky*64+o] (33.5MB)

__device__ __forceinline__ float silu_f(float t) {
    return t / (1.0f + __expf(-t));
}

// ---------------- twiddle init ----------------
__global__ void k_init() {
    int t = blockIdx.x * blockDim.x + threadIdx.x;   // 16384 threads
    {
        // T2aT[w][r]: r = p*32+ky; p=0: cos(2pi ky w/256), p=1: -sin
        int w = t >> 6, r = t & 63;
        int p = r >> 5, ky = r & 31;
        float s, c;
        sincospif((float)((ky * w) & 255) * (1.0f / 128.0f), &s, &c);
        g_T2aT[w * 64 + r] = p ? -s : c;
    }
    {
        // T1T[h][m]: m<64 cos(2pi kx h/256), m>=64 sin
        int h = t >> 6, k = t & 63;
        int kx = (k < 32) ? k : 192 + k;
        float s, c;
        sincospif((float)((kx * h) & 255) * (1.0f / 128.0f), &s, &c);
        g_T1T[h * 128 + k]      = c;
        g_T1T[h * 128 + 64 + k] = s;
    }
    {
        // T4T[kxp][hp]: inverse e^{+i2pi kx h/256}
        // Gre = Fre*c - Fim*s ; Gim = Fre*s + Fim*c
        int h = t >> 6, k = t & 63;
        int kx = (k < 32) ? k : 192 + k;
        float s, c;
        sincospif((float)((kx * h) & 255) * (1.0f / 128.0f), &s, &c);
        g_T4T[(2 * k)     * 512 + 2 * h]     = c;
        g_T4T[(2 * k + 1) * 512 + 2 * h]     = -s;
        g_T4T[(2 * k)     * 512 + 2 * h + 1] = s;
        g_T4T[(2 * k + 1) * 512 + 2 * h + 1] = c;
    }
    {
        // T5t[kyp][w]: y[w] = sum_ky c_ky*(Gre*cos - Gim*sin), c_0=1 else 2
        int r = t >> 8, w = t & 255;
        int ky = r >> 1, p = r & 1;
        float s, c;
        sincospif((float)((ky * w) & 255) * (1.0f / 128.0f), &s, &c);
        float f = (ky == 0) ? 1.0f : 2.0f;
        g_T5t[r * 256 + w] = p ? -f * s : f * c;
    }
}

// ---------------- residual: d_out = x @ res_w + res_b ----------------
__global__ void __launch_bounds__(256) k_resid(const float* __restrict__ x,
                                               const float* __restrict__ rw,
                                               const float* __restrict__ rb,
                                               float* __restrict__ out) {
    extern __shared__ float sm[];
    float(*As)[260] = (float(*)[260])sm;            // [64 k][256 m(+pad)]
    float(*Bs)[68]  = (float(*)[68])(sm + 64 * 260); // [64 k][64 o(+pad)]
    float* bb = sm + 64 * 260 + 64 * 68;
    int tid = threadIdx.x;
    const float* xb = x + (size_t)blockIdx.x * 16384;
#pragma unroll
    for (int q = 0; q < 16; q++) {
        int f4 = tid + q * 256;
        int m = f4 >> 4, j = f4 & 15;
        float4 v = *(const float4*)(xb + m * 64 + j * 4);
        As[j * 4 + 0][m] = v.x; As[j * 4 + 1][m] = v.y;
        As[j * 4 + 2][m] = v.z; As[j * 4 + 3][m] = v.w;
    }
#pragma unroll
    for (int q = 0; q < 4; q++) {
        int f4 = tid + q * 256;
        int k = f4 >> 4, j = f4 & 15;
        *(float4*)&Bs[k][j * 4] = *(const float4*)(rw + k * 64 + j * 4);
    }
    if (tid < 64) bb[tid] = rb[tid];
    __syncthreads();
    int r0 = (tid >> 3) * 8, c0 = (tid & 7) * 8;
    float acc[8][8];
#pragma unroll
    for (int i = 0; i < 8; i++)
#pragma unroll
        for (int j = 0; j < 8; j++) acc[i][j] = bb[c0 + j];
#pragma unroll 4
    for (int k = 0; k < 64; k++) {
        float a[8], b[8];
        *(float4*)(a)     = *(float4*)&As[k][r0];
        *(float4*)(a + 4) = *(float4*)&As[k][r0 + 4];
        *(float4*)(b)     = *(float4*)&Bs[k][c0];
        *(float4*)(b + 4) = *(float4*)&Bs[k][c0 + 4];
#pragma unroll
        for (int i = 0; i < 8; i++)
#pragma unroll
            for (int j = 0; j < 8; j++) acc[i][j] += a[i] * b[j];
    }
    float* ob = out + (size_t)blockIdx.x * 16384;
#pragma unroll
    for (int i = 0; i < 8; i++) {
        int m = r0 + i;
        *(float4*)(ob + m * 64 + c0)     = make_float4(acc[i][0], acc[i][1], acc[i][2], acc[i][3]);
        *(float4*)(ob + m * 64 + c0 + 4) = make_float4(acc[i][4], acc[i][5], acc[i][6], acc[i][7]);
    }
}

// ---------------- Stage A: w-DFT first ----------------
// block = (n, h-pair): Xw[64 r][128 (hl,i)] = T2a[64][256] @ x[n,h0..h0+1][256 w][64 i]
__global__ void __launch_bounds__(256) k_a(const float* __restrict__ x) {
    __shared__ float As[32][68];    // [k][r]
    __shared__ float Bs[32][128];   // [k][(hl,i)]
    int tid = threadIdx.x;
    int n = blockIdx.x >> 7;
    int h0 = (blockIdx.x & 127) * 2;
    const float* B = x + (size_t)n * 4194304 + (size_t)h0 * 16384;
    float acc[8][4] = {};
    int r0 = (tid >> 5) * 8, c0 = (tid & 31) * 4;
    for (int kc = 0; kc < 256; kc += 32) {
#pragma unroll
        for (int q = 0; q < 2; q++) {
            int e = tid + q * 256;           // 512 f4 : 32k x 16 r4
            int kk = e >> 4, r4 = e & 15;
            *(float4*)&As[kk][r4 * 4] = *(const float4*)(g_T2aT + (kc + kk) * 64 + r4 * 4);
        }
#pragma unroll
        for (int q = 0; q < 4; q++) {
            int e = tid + q * 256;           // 1024 f4 : 32k x 32 c4
            int kk = e >> 5, c4 = e & 31;
            int hl = c4 >> 4, i4 = c4 & 15;
            *(float4*)&Bs[kk][c4 * 4] =
                *(const float4*)(B + hl * 16384 + (kc + kk) * 64 + i4 * 4);
        }
        __syncthreads();
#pragma unroll 8
        for (int k = 0; k < 32; k++) {
            float a[8], b[4];
            *(float4*)(a)     = *(float4*)&As[k][r0];
            *(float4*)(a + 4) = *(float4*)&As[k][r0 + 4];
            *(float4*)(b)     = *(float4*)&Bs[k][c0];
#pragma unroll
            for (int i = 0; i < 8; i++)
#pragma unroll
                for (int j = 0; j < 4; j++) acc[i][j] += a[i] * b[j];
        }
        __syncthreads();
    }
    int hl = c0 >> 6, i = c0 & 63;
    float* O = g_Xw + (size_t)n * 1048576 + (size_t)(h0 + hl) * 4096 + i;
#pragma unroll
    for (int r = 0; r < 8; r++) {
        *(float4*)(O + (r0 + r) * 64) = make_float4(acc[r][0], acc[r][1], acc[r][2], acc[r][3]);
    }
}

// ---------------- Stage B: h-DFT (cos & sin planes) ----------------
// per n: C[128][4096] = T1cs[128][256] @ Xw[n][256 h][4096]
__global__ void __launch_bounds__(256) k_b() {
    __shared__ float As[16][132];
    __shared__ float Bs[16][128];
    int tid = threadIdx.x;
    int n = blockIdx.y;
    int colbase = blockIdx.x * 128;
    const float* B = g_Xw + (size_t)n * 1048576;
    float acc[8][8] = {};
    int r0 = (tid >> 4) * 8, c0 = (tid & 15) * 8;
    for (int kc = 0; kc < 256; kc += 16) {
#pragma unroll
        for (int q = 0; q < 2; q++) {
            int e = tid + q * 256;
            int kk = e >> 5, m4 = e & 31;
            *(float4*)&As[kk][m4 * 4] = *(const float4*)(g_T1T + (kc + kk) * 128 + m4 * 4);
        }
#pragma unroll
        for (int q = 0; q < 2; q++) {
            int e = tid + q * 256;
            int kk = e >> 5, c4 = e & 31;
            *(float4*)&Bs[kk][c4 * 4] =
                *(const float4*)(B + (size_t)(kc + kk) * 4096 + colbase + c4 * 4);
        }
        __syncthreads();
#pragma unroll 4
        for (int k = 0; k < 16; k++) {
            float a[8], b[8];
            *(float4*)(a)     = *(float4*)&As[k][r0];
            *(float4*)(a + 4) = *(float4*)&As[k][r0 + 4];
            *(float4*)(b)     = *(float4*)&Bs[k][c0];
            *(float4*)(b + 4) = *(float4*)&Bs[k][c0 + 4];
#pragma unroll
            for (int i = 0; i < 8; i++)
#pragma unroll
                for (int j = 0; j < 8; j++) acc[i][j] += a[i] * b[j];
        }
        __syncthreads();
    }
    float* C = g_C + (size_t)n * 524288 + colbase;
#pragma unroll
    for (int i = 0; i < 8; i++) {
        int row = r0 + i;
        *(float4*)(C + (size_t)row * 4096 + c0)     = make_float4(acc[i][0], acc[i][1], acc[i][2], acc[i][3]);
        *(float4*)(C + (size_t)row * 4096 + c0 + 4) = make_float4(acc[i][4], acc[i][5], acc[i][6], acc[i][7]);
    }
}

// ---------------- S3: complex recombine + mode channel mix, scale 1/65536 ----------------
__global__ void __launch_bounds__(256) k_c(const float* __restrict__ w0,
                                           const float* __restrict__ w1) {
    __shared__ float Wre[64][64], Wim[64][64];
    __shared__ float Xre[8][64], Xim[8][64];
    int tid = threadIdx.x;
    int ky = blockIdx.x & 31, k = blockIdx.x >> 5;
    const float* W = (k < 32) ? (w0 + (size_t)(k * 32 + ky) * 4096 * 2)
                              : (w1 + (size_t)((k - 32) * 32 + ky) * 4096 * 2);
#pragma unroll
    for (int q = 0; q < 16; q++) {
        int e = tid + q * 256;          // i*64+o
        float2 v = *(const float2*)(W + (size_t)e * 2);
        Wre[e >> 6][e & 63] = v.x;
        Wim[e >> 6][e & 63] = v.y;
    }
#pragma unroll
    for (int q = 0; q < 2; q++) {
        int e = tid + q * 256;          // n*64+i
        int n = e >> 6, i = e & 63;
        const float* Cn = g_C + (size_t)n * 524288;
        float cc0 = Cn[(size_t)k * 4096 + ky * 64 + i];               // Ccos, re-plane
        float cc1 = Cn[(size_t)k * 4096 + 2048 + ky * 64 + i];        // Ccos, im-plane
        float cs0 = Cn[(size_t)(64 + k) * 4096 + ky * 64 + i];        // Csin, re-plane
        float cs1 = Cn[(size_t)(64 + k) * 4096 + 2048 + ky * 64 + i]; // Csin, im-plane
        Xre[n][i] = cc0 + cs1;
        Xim[n][i] = cc1 - cs0;
    }
    __syncthreads();
    const float sc = 1.0f / 65536.0f;
#pragma unroll
    for (int q = 0; q < 2; q++) {
        int e = tid + q * 256;
        int n = e >> 6, o = e & 63;
        float fre = 0.0f, fim = 0.0f;
#pragma unroll 8
        for (int i = 0; i < 64; i++) {
            float xr = Xre[n][i], xi = Xim[n][i];
            float wr = Wre[i][o], wi = Wim[i][o];
            fre += xr * wr - xi * wi;
            fim += xr * wi + xi * wr;
        }
        g_F[((size_t)(n * 128 + 2 * k) * 32 + ky) * 64 + o]     = fre * sc;
        g_F[((size_t)(n * 128 + 2 * k + 1) * 32 + ky) * 64 + o] = fim * sc;
    }
}

// ---------------- S4: per n: G[512 hp][2048] = T4[512][128] @ F[n][128][2048] ----------------
__global__ void __launch_bounds__(256) k_s4() {
    __shared__ float As[16][132];
    __shared__ float Bs[16][128];
    int tid = threadIdx.x;
    int colbase = blockIdx.x * 128;
    int m0 = blockIdx.y * 128;
    int n = blockIdx.z;
    const float* B = g_F + (size_t)n * 128 * 2048;
    float acc[8][8] = {};
    int r0 = (tid >> 4) * 8, c0 = (tid & 15) * 8;
    for (int kc = 0; kc < 128; kc += 16) {
#pragma unroll
        for (int q = 0; q < 2; q++) {
            int e = tid + q * 256;
            int kk = e >> 5, m4 = e & 31;
            *(float4*)&As[kk][m4 * 4] =
                *(const float4*)(g_T4T + (size_t)(kc + kk) * 512 + m0 + m4 * 4);
        }
#pragma unroll
        for (int q = 0; q < 2; q++) {
            int e = tid + q * 256;
            int kk = e >> 5, c4 = e & 31;
            *(float4*)&Bs[kk][c4 * 4] =
                *(const float4*)(B + (size_t)(kc + kk) * 2048 + colbase + c4 * 4);
        }
        __syncthreads();
#pragma unroll 4
        for (int k = 0; k < 16; k++) {
            float a[8], b[8];
            *(float4*)(a)     = *(float4*)&As[k][r0];
            *(float4*)(a + 4) = *(float4*)&As[k][r0 + 4];
            *(float4*)(b)     = *(float4*)&Bs[k][c0];
            *(float4*)(b + 4) = *(float4*)&Bs[k][c0 + 4];
#pragma unroll
            for (int i = 0; i < 8; i++)
#pragma unroll
                for (int j = 0; j < 8; j++) acc[i][j] += a[i] * b[j];
        }
        __syncthreads();
    }
    float* C = g_G + (size_t)n * 512 * 2048 + colbase;
#pragma unroll
    for (int i = 0; i < 8; i++) {
        int row = m0 + r0 + i;
        *(float4*)(C + (size_t)row * 2048 + c0)     = make_float4(acc[i][0], acc[i][1], acc[i][2], acc[i][3]);
        *(float4*)(C + (size_t)row * 2048 + c0 + 4) = make_float4(acc[i][4], acc[i][5], acc[i][6], acc[i][7]);
    }
}

// ---------------- S5: per (n,h): y = T5t^T @ G + res, silu ----------------
__global__ void __launch_bounds__(256) k_s5(float* __restrict__ out) {
    extern __shared__ float sm[];
    float(*As)[260] = (float(*)[260])sm;             // [64 kyp][256 w(+pad)]
    float(*Bs)[68]  = (float(*)[68])(sm + 64 * 260);  // [64 kyp][64 o(+pad)]
    int tid = threadIdx.x;
    int h = blockIdx.x & 255, n = blockIdx.x >> 8;
#pragma unroll
    for (int q = 0; q < 16; q++) {
        int e = tid + q * 256;           // 4096 f4 : 64 rows x 64 w4
        int k = e >> 6, w4 = e & 63;
        *(float4*)&As[k][w4 * 4] = *(const float4*)(g_T5t + k * 256 + w4 * 4);
    }
    const float* G = g_G + (size_t)(n * 256 + h) * 4096;  // [p][ky][o]
#pragma unroll
    for (int q = 0; q < 4; q++) {
        int e4 = tid + q * 256;          // 1024 f4
        int p = e4 >> 9, ky = (e4 >> 4) & 31, j = e4 & 15;
        float4 v = *(const float4*)(G + p * 2048 + ky * 64 + j * 4);
        *(float4*)&Bs[2 * ky + p][j * 4] = v;
    }
    __syncthreads();
    int r0 = (tid >> 3) * 8, c0 = (tid & 7) * 8;
    float acc[8][8] = {};
#pragma unroll 4
    for (int k = 0; k < 64; k++) {
        float a[8], b[8];
        *(float4*)(a)     = *(float4*)&As[k][r0];
        *(float4*)(a + 4) = *(float4*)&As[k][r0 + 4];
        *(float4*)(b)     = *(float4*)&Bs[k][c0];
        *(float4*)(b + 4) = *(float4*)&Bs[k][c0 + 4];
#pragma unroll
        for (int i = 0; i < 8; i++)
#pragma unroll
            for (int j = 0; j < 8; j++) acc[i][j] += a[i] * b[j];
    }
    float* ob = out + (size_t)(n * 256 + h) * 16384;   // [w][o], currently holds residual
#pragma unroll
    for (int i = 0; i < 8; i++) {
        int w = r0 + i;
        float4 rv0 = *(float4*)(ob + w * 64 + c0);
        float4 rv1 = *(float4*)(ob + w * 64 + c0 + 4);
        float4 o0, o1;
        o0.x = silu_f(acc[i][0] + rv0.x); o0.y = silu_f(acc[i][1] + rv0.y);
        o0.z = silu_f(acc[i][2] + rv0.z); o0.w = silu_f(acc[i][3] + rv0.w);
        o1.x = silu_f(acc[i][4] + rv1.x); o1.y = silu_f(acc[i][5] + rv1.y);
        o1.z = silu_f(acc[i][6] + rv1.z); o1.w = silu_f(acc[i][7] + rv1.w);
        *(float4*)(ob + w * 64 + c0)     = o0;
        *(float4*)(ob + w * 64 + c0 + 4) = o1;
    }
}

// ---------------- launch ----------------
extern "C" void kernel_launch(void* const* d_in, const int* in_sizes, int n_in,
                              void* d_out, int out_size) {
    const float* x  = (const float*)d_in[0];
    const float* w0 = (const float*)d_in[1];
    const float* w1 = (const float*)d_in[2];
    const float* rw = (const float*)d_in[3];
    const float* rb = (const float*)d_in[4];
    float* out = (float*)d_out;

    const int SMEM_BIG = (64 * 260 + 64 * 68 + 64) * 4;   // 84224 bytes
    cudaFuncSetAttribute(k_resid, cudaFuncAttributeMaxDynamicSharedMemorySize, SMEM_BIG);
    cudaFuncSetAttribute(k_s5,    cudaFuncAttributeMaxDynamicSharedMemorySize, SMEM_BIG);

    k_init<<<64, 256>>>();
    k_resid<<<2048, 256, SMEM_BIG>>>(x, rw, rb, out);
    k_a<<<1024, 256>>>(x);
    dim3 gb(32, 8);
    k_b<<<gb, 256>>>();
    k_c<<<2048, 256>>>(w0, w1);
    dim3 g4(16, 4, 8);
    k_s4<<<g4, 256>>>();
    k_s5<<<2048, 256, SMEM_BIG>>>(out);
}

// round 8
// speedup vs baseline: 1.2973x; 1.0151x over previous
#include <cuda_runtime.h>
#include <math.h>

// Problem constants: N=8, R=256, IN=64, OUT=64, MODE=32
// kx mode list (64): k<32 -> kx=k ; k>=32 -> kx=192+k

// ---------------- device scratch ----------------
__device__ float g_T2aT[256 * 64];    // fwd w-DFT, transposed: [w][r=p*32+ky]
__device__ float g_T1T[256 * 128];    // fwd h-DFT cos/sin, transposed: [h][m] m<64:cos m>=64:sin
__device__ float g_T4T[128 * 512];    // inv h-DFT, transposed: [kxp][hp]
__device__ float g_T5t[64 * 256];     // inv w-DFT, transposed: [kyp][w]
__device__ float g_Xw[(size_t)8 * 256 * 4096];  // [n][h][p*2048+ky*64+i]  (33.5MB)
__device__ float g_C [(size_t)8 * 128 * 4096];  // [n][m(cos|sin)][p*2048+ky*64+i] (16.8MB)
__device__ float g_F [(size_t)8 * 128 * 32 * 64]; // [n][kxp][ky][o] (8.4MB)
__device__ float g_G [(size_t)8 * 512 * 2048];    // [n][hp][ky*64+o] (33.5MB)

__device__ __forceinline__ float silu_f(float t) {
    return t / (1.0f + __expf(-t));
}

// ---------------- twiddle init ----------------
__global__ void k_init() {
    int t = blockIdx.x * blockDim.x + threadIdx.x;   // 16384 threads
    {
        int w = t >> 6, r = t & 63;
        int p = r >> 5, ky = r & 31;
        float s, c;
        sincospif((float)((ky * w) & 255) * (1.0f / 128.0f), &s, &c);
        g_T2aT[w * 64 + r] = p ? -s : c;
    }
    {
        int h = t >> 6, k = t & 63;
        int kx = (k < 32) ? k : 192 + k;
        float s, c;
        sincospif((float)((kx * h) & 255) * (1.0f / 128.0f), &s, &c);
        g_T1T[h * 128 + k]      = c;
        g_T1T[h * 128 + 64 + k] = s;
    }
    {
        int h = t >> 6, k = t & 63;
        int kx = (k < 32) ? k : 192 + k;
        float s, c;
        sincospif((float)((kx * h) & 255) * (1.0f / 128.0f), &s, &c);
        g_T4T[(2 * k)     * 512 + 2 * h]     = c;
        g_T4T[(2 * k + 1) * 512 + 2 * h]     = -s;
        g_T4T[(2 * k)     * 512 + 2 * h + 1] = s;
        g_T4T[(2 * k + 1) * 512 + 2 * h + 1] = c;
    }
    {
        int r = t >> 8, w = t & 255;
        int ky = r >> 1, p = r & 1;
        float s, c;
        sincospif((float)((ky * w) & 255) * (1.0f / 128.0f), &s, &c);
        float f = (ky == 0) ? 1.0f : 2.0f;
        g_T5t[r * 256 + w] = p ? -f * s : f * c;
    }
}

// ---------------- Stage A: w-DFT first (double-buffered) ----------------
// block = (n, 4 h rows): Xw[64 r][256 (hl,i)] = T2a[64][256] @ x[n,h0..h0+3]
__global__ void __launch_bounds__(256, 2) k_a(const float* __restrict__ x) {
    __shared__ float As[2][16][68];    // [k][r]
    __shared__ float Bs[2][16][256];   // [k][(hl,i)]
    int tid = threadIdx.x;
    int n = blockIdx.x >> 6;
    int h0 = (blockIdx.x & 63) * 4;
    const float* B = x + (size_t)n * 4194304 + (size_t)h0 * 16384;
    float acc[8][8] = {};
    int r0 = (tid >> 5) * 8, c0 = (tid & 31) * 8;
    int ka = tid >> 4, ra4 = tid & 15;   // A: 256 f4/chunk, 1 per thread

    float4 pa;
    float4 pb[4];
    // prologue: chunk 0
    pa = *(const float4*)(g_T2aT + ka * 64 + ra4 * 4);
#pragma unroll
    for (int q = 0; q < 4; q++) {
        int e = tid + q * 256;
        int kk = e >> 6, c4 = e & 63;
        int hl = c4 >> 4, i4 = c4 & 15;
        pb[q] = *(const float4*)(B + hl * 16384 + kk * 64 + i4 * 4);
    }
    *(float4*)&As[0][ka][ra4 * 4] = pa;
#pragma unroll
    for (int q = 0; q < 4; q++) {
        int e = tid + q * 256;
        int kk = e >> 6, c4 = e & 63;
        *(float4*)&Bs[0][kk][c4 * 4] = pb[q];
    }
    __syncthreads();
    int buf = 0;
    for (int kc = 0; kc < 256; kc += 16) {
        if (kc + 16 < 256) {
            pa = *(const float4*)(g_T2aT + (kc + 16 + ka) * 64 + ra4 * 4);
#pragma unroll
            for (int q = 0; q < 4; q++) {
                int e = tid + q * 256;
                int kk = e >> 6, c4 = e & 63;
                int hl = c4 >> 4, i4 = c4 & 15;
                pb[q] = *(const float4*)(B + hl * 16384 + (kc + 16 + kk) * 64 + i4 * 4);
            }
        }
#pragma unroll
        for (int k = 0; k < 16; k++) {
            float a[8], b[8];
            *(float4*)(a)     = *(float4*)&As[buf][k][r0];
            *(float4*)(a + 4) = *(float4*)&As[buf][k][r0 + 4];
            *(float4*)(b)     = *(float4*)&Bs[buf][k][c0];
            *(float4*)(b + 4) = *(float4*)&Bs[buf][k][c0 + 4];
#pragma unroll
            for (int i = 0; i < 8; i++)
#pragma unroll
                for (int j = 0; j < 8; j++) acc[i][j] += a[i] * b[j];
        }
        if (kc + 16 < 256) {
            *(float4*)&As[buf ^ 1][ka][ra4 * 4] = pa;
#pragma unroll
            for (int q = 0; q < 4; q++) {
                int e = tid + q * 256;
                int kk = e >> 6, c4 = e & 63;
                *(float4*)&Bs[buf ^ 1][kk][c4 * 4] = pb[q];
            }
        }
        __syncthreads();
        buf ^= 1;
    }
    // output: row r -> p=r>>5, ky=r&31 ; col c0 -> hl=c0>>6, i=c0&63
    int hl = c0 >> 6, i = c0 & 63;
    int p0 = r0 >> 5;
    float* O = g_Xw + (size_t)n * 1048576 + (size_t)(h0 + hl) * 4096 + (size_t)p0 * 2048 + i;
#pragma unroll
    for (int r = 0; r < 8; r++) {
        int ky = (r0 + r) & 31;
        *(float4*)(O + ky * 64)     = make_float4(acc[r][0], acc[r][1], acc[r][2], acc[r][3]);
        *(float4*)(O + ky * 64 + 4) = make_float4(acc[r][4], acc[r][5], acc[r][6], acc[r][7]);
    }
}

// ---------------- Stage B: h-DFT (cos & sin planes), double-buffered ----------------
// per n: C[128][4096] = T1cs[128][256] @ Xw[n][256 h][4096]
__global__ void __launch_bounds__(256, 2) k_b() {
    __shared__ float As[2][16][132];
    __shared__ float Bs[2][16][128];
    int tid = threadIdx.x;
    int n = blockIdx.y;
    int colbase = blockIdx.x * 128;
    const float* B = g_Xw + (size_t)n * 1048576;
    float acc[8][8] = {};
    int r0 = (tid >> 4) * 8, c0 = (tid & 15) * 8;

    float4 pa[2], pb[2];
#pragma unroll
    for (int q = 0; q < 2; q++) {
        int e = tid + q * 256;
        int kk = e >> 5, m4 = e & 31;
        pa[q] = *(const float4*)(g_T1T + kk * 128 + m4 * 4);
        pb[q] = *(const float4*)(B + (size_t)kk * 4096 + colbase + m4 * 4);
    }
#pragma unroll
    for (int q = 0; q < 2; q++) {
        int e = tid + q * 256;
        int kk = e >> 5, m4 = e & 31;
        *(float4*)&As[0][kk][m4 * 4] = pa[q];
        *(float4*)&Bs[0][kk][m4 * 4] = pb[q];
    }
    __syncthreads();
    int buf = 0;
    for (int kc = 0; kc < 256; kc += 16) {
        if (kc + 16 < 256) {
#pragma unroll
            for (int q = 0; q < 2; q++) {
                int e = tid + q * 256;
                int kk = e >> 5, m4 = e & 31;
                pa[q] = *(const float4*)(g_T1T + (kc + 16 + kk) * 128 + m4 * 4);
                pb[q] = *(const float4*)(B + (size_t)(kc + 16 + kk) * 4096 + colbase + m4 * 4);
            }
        }
#pragma unroll
        for (int k = 0; k < 16; k++) {
            float a[8], b[8];
            *(float4*)(a)     = *(float4*)&As[buf][k][r0];
            *(float4*)(a + 4) = *(float4*)&As[buf][k][r0 + 4];
            *(float4*)(b)     = *(float4*)&Bs[buf][k][c0];
            *(float4*)(b + 4) = *(float4*)&Bs[buf][k][c0 + 4];
#pragma unroll
            for (int i = 0; i < 8; i++)
#pragma unroll
                for (int j = 0; j < 8; j++) acc[i][j] += a[i] * b[j];
        }
        if (kc + 16 < 256) {
#pragma unroll
            for (int q = 0; q < 2; q++) {
                int e = tid + q * 256;
                int kk = e >> 5, m4 = e & 31;
                *(float4*)&As[buf ^ 1][kk][m4 * 4] = pa[q];
                *(float4*)&Bs[buf ^ 1][kk][m4 * 4] = pb[q];
            }
        }
        __syncthreads();
        buf ^= 1;
    }
    float* C = g_C + (size_t)n * 524288 + colbase;
#pragma unroll
    for (int i = 0; i < 8; i++) {
        int row = r0 + i;
        *(float4*)(C + (size_t)row * 4096 + c0)     = make_float4(acc[i][0], acc[i][1], acc[i][2], acc[i][3]);
        *(float4*)(C + (size_t)row * 4096 + c0 + 4) = make_float4(acc[i][4], acc[i][5], acc[i][6], acc[i][7]);
    }
}

// ---------------- S3: complex recombine + mode channel mix, scale 1/65536 ----------------
__global__ void __launch_bounds__(256) k_c(const float* __restrict__ w0,
                                           const float* __restrict__ w1) {
    __shared__ float Wre[64][64], Wim[64][64];
    __shared__ float Xre[8][64], Xim[8][64];
    int tid = threadIdx.x;
    int ky = blockIdx.x & 31, k = blockIdx.x >> 5;
    const float* W = (k < 32) ? (w0 + (size_t)(k * 32 + ky) * 4096 * 2)
                              : (w1 + (size_t)((k - 32) * 32 + ky) * 4096 * 2);
#pragma unroll
    for (int q = 0; q < 16; q++) {
        int e = tid + q * 256;          // i*64+o
        float2 v = *(const float2*)(W + (size_t)e * 2);
        Wre[e >> 6][e & 63] = v.x;
        Wim[e >> 6][e & 63] = v.y;
    }
#pragma unroll
    for (int q = 0; q < 2; q++) {
        int e = tid + q * 256;          // n*64+i
        int n = e >> 6, i = e & 63;
        const float* Cn = g_C + (size_t)n * 524288;
        float cc0 = Cn[(size_t)k * 4096 + ky * 64 + i];
        float cc1 = Cn[(size_t)k * 4096 + 2048 + ky * 64 + i];
        float cs0 = Cn[(size_t)(64 + k) * 4096 + ky * 64 + i];
        float cs1 = Cn[(size_t)(64 + k) * 4096 + 2048 + ky * 64 + i];
        Xre[n][i] = cc0 + cs1;
        Xim[n][i] = cc1 - cs0;
    }
    __syncthreads();
    const float sc = 1.0f / 65536.0f;
#pragma unroll
    for (int q = 0; q < 2; q++) {
        int e = tid + q * 256;
        int n = e >> 6, o = e & 63;
        float fre = 0.0f, fim = 0.0f;
#pragma unroll 8
        for (int i = 0; i < 64; i++) {
            float xr = Xre[n][i], xi = Xim[n][i];
            float wr = Wre[i][o], wi = Wim[i][o];
            fre += xr * wr - xi * wi;
            fim += xr * wi + xi * wr;
        }
        g_F[((size_t)(n * 128 + 2 * k) * 32 + ky) * 64 + o]     = fre * sc;
        g_F[((size_t)(n * 128 + 2 * k + 1) * 32 + ky) * 64 + o] = fim * sc;
    }
}

// ---------------- S4: per n: G[512 hp][2048] = T4[512][128] @ F[n], double-buffered ----------------
__global__ void __launch_bounds__(256, 2) k_s4() {
    __shared__ float As[2][16][132];
    __shared__ float Bs[2][16][128];
    int tid = threadIdx.x;
    int colbase = blockIdx.x * 128;
    int m0 = blockIdx.y * 128;
    int n = blockIdx.z;
    const float* B = g_F + (size_t)n * 128 * 2048;
    float acc[8][8] = {};
    int r0 = (tid >> 4) * 8, c0 = (tid & 15) * 8;

    float4 pa[2], pb[2];
#pragma unroll
    for (int q = 0; q < 2; q++) {
        int e = tid + q * 256;
        int kk = e >> 5, m4 = e & 31;
        pa[q] = *(const float4*)(g_T4T + (size_t)kk * 512 + m0 + m4 * 4);
        pb[q] = *(const float4*)(B + (size_t)kk * 2048 + colbase + m4 * 4);
    }
#pragma unroll
    for (int q = 0; q < 2; q++) {
        int e = tid + q * 256;
        int kk = e >> 5, m4 = e & 31;
        *(float4*)&As[0][kk][m4 * 4] = pa[q];
        *(float4*)&Bs[0][kk][m4 * 4] = pb[q];
    }
    __syncthreads();
    int buf = 0;
    for (int kc = 0; kc < 128; kc += 16) {
        if (kc + 16 < 128) {
#pragma unroll
            for (int q = 0; q < 2; q++) {
                int e = tid + q * 256;
                int kk = e >> 5, m4 = e & 31;
                pa[q] = *(const float4*)(g_T4T + (size_t)(kc + 16 + kk) * 512 + m0 + m4 * 4);
                pb[q] = *(const float4*)(B + (size_t)(kc + 16 + kk) * 2048 + colbase + m4 * 4);
            }
        }
#pragma unroll
        for (int k = 0; k < 16; k++) {
            float a[8], b[8];
            *(float4*)(a)     = *(float4*)&As[buf][k][r0];
            *(float4*)(a + 4) = *(float4*)&As[buf][k][r0 + 4];
            *(float4*)(b)     = *(float4*)&Bs[buf][k][c0];
            *(float4*)(b + 4) = *(float4*)&Bs[buf][k][c0 + 4];
#pragma unroll
            for (int i = 0; i < 8; i++)
#pragma unroll
                for (int j = 0; j < 8; j++) acc[i][j] += a[i] * b[j];
        }
        if (kc + 16 < 128) {
#pragma unroll
            for (int q = 0; q < 2; q++) {
                int e = tid + q * 256;
                int kk = e >> 5, m4 = e & 31;
                *(float4*)&As[buf ^ 1][kk][m4 * 4] = pa[q];
                *(float4*)&Bs[buf ^ 1][kk][m4 * 4] = pb[q];
            }
        }
        __syncthreads();
        buf ^= 1;
    }
    float* C = g_G + (size_t)n * 512 * 2048 + colbase;
#pragma unroll
    for (int i = 0; i < 8; i++) {
        int row = m0 + r0 + i;
        *(float4*)(C + (size_t)row * 2048 + c0)     = make_float4(acc[i][0], acc[i][1], acc[i][2], acc[i][3]);
        *(float4*)(C + (size_t)row * 2048 + c0 + 4) = make_float4(acc[i][4], acc[i][5], acc[i][6], acc[i][7]);
    }
}

// ---------------- S5 (fused with residual): per (n,h):
//   y[w][o] = T5t^T @ G  +  x[n,h]^T-GEMM res_w  + res_b, then silu ----------------
__global__ void __launch_bounds__(256) k_s5(const float* __restrict__ x,
                                            const float* __restrict__ rw,
                                            const float* __restrict__ rb,
                                            float* __restrict__ out) {
    extern __shared__ float sm[];
    float(*As)[260] = (float(*)[260])sm;             // [64 k][256 w(+pad)]
    float(*Bs)[68]  = (float(*)[68])(sm + 64 * 260);  // [64 k][64 o(+pad)]
    float* bb = sm + 64 * 260 + 64 * 68;
    int tid = threadIdx.x;
    int h = blockIdx.x & 255, n = blockIdx.x >> 8;
    int r0 = (tid >> 3) * 8, c0 = (tid & 7) * 8;
    float acc[8][8] = {};

    // ----- pass 1: spectral  As=T5t [kyp][w], Bs=G [kyp][o] -----
#pragma unroll
    for (int q = 0; q < 16; q++) {
        int e = tid + q * 256;           // 4096 f4 : 64 rows x 64 w4
        int k = e >> 6, w4 = e & 63;
        *(float4*)&As[k][w4 * 4] = *(const float4*)(g_T5t + k * 256 + w4 * 4);
    }
    const float* G = g_G + (size_t)(n * 256 + h) * 4096;  // [p][ky][o]
#pragma unroll
    for (int q = 0; q < 4; q++) {
        int e4 = tid + q * 256;          // 1024 f4
        int p = e4 >> 9, ky = (e4 >> 4) & 31, j = e4 & 15;
        float4 v = *(const float4*)(G + p * 2048 + ky * 64 + j * 4);
        *(float4*)&Bs[2 * ky + p][j * 4] = v;
    }
    __syncthreads();
#pragma unroll 4
    for (int k = 0; k < 64; k++) {
        float a[8], b[8];
        *(float4*)(a)     = *(float4*)&As[k][r0];
        *(float4*)(a + 4) = *(float4*)&As[k][r0 + 4];
        *(float4*)(b)     = *(float4*)&Bs[k][c0];
        *(float4*)(b + 4) = *(float4*)&Bs[k][c0 + 4];
#pragma unroll
        for (int i = 0; i < 8; i++)
#pragma unroll
            for (int j = 0; j < 8; j++) acc[i][j] += a[i] * b[j];
    }
    __syncthreads();

    // ----- pass 2: residual  As=x[n,h]^T [i][w], Bs=rw [i][o] -----
    const float* xb = x + (size_t)(n * 256 + h) * 16384;   // [w][i]
#pragma unroll
    for (int q = 0; q < 16; q++) {
        int f4 = tid + q * 256;          // 4096 f4 : 256 w x 16 i4
        int w = f4 >> 4, j = f4 & 15;
        float4 v = *(const float4*)(xb + w * 64 + j * 4);
        As[j * 4 + 0][w] = v.x; As[j * 4 + 1][w] = v.y;
        As[j * 4 + 2][w] = v.z; As[j * 4 + 3][w] = v.w;
    }
#pragma unroll
    for (int q = 0; q < 4; q++) {
        int f4 = tid + q * 256;
        int k = f4 >> 4, j = f4 & 15;
        *(float4*)&Bs[k][j * 4] = *(const float4*)(rw + k * 64 + j * 4);
    }
    if (tid < 64) bb[tid] = rb[tid];
    __syncthreads();
#pragma unroll 4
    for (int k = 0; k < 64; k++) {
        float a[8], b[8];
        *(float4*)(a)     = *(float4*)&As[k][r0];
        *(float4*)(a + 4) = *(float4*)&As[k][r0 + 4];
        *(float4*)(b)     = *(float4*)&Bs[k][c0];
        *(float4*)(b + 4) = *(float4*)&Bs[k][c0 + 4];
#pragma unroll
        for (int i = 0; i < 8; i++)
#pragma unroll
            for (int j = 0; j < 8; j++) acc[i][j] += a[i] * b[j];
    }

    float* ob = out + (size_t)(n * 256 + h) * 16384;   // [w][o]
#pragma unroll
    for (int i = 0; i < 8; i++) {
        int w = r0 + i;
        float4 o0, o1;
        o0.x = silu_f(acc[i][0] + bb[c0 + 0]); o0.y = silu_f(acc[i][1] + bb[c0 + 1]);
        o0.z = silu_f(acc[i][2] + bb[c0 + 2]); o0.w = silu_f(acc[i][3] + bb[c0 + 3]);
        o1.x = silu_f(acc[i][4] + bb[c0 + 4]); o1.y = silu_f(acc[i][5] + bb[c0 + 5]);
        o1.z = silu_f(acc[i][6] + bb[c0 + 6]); o1.w = silu_f(acc[i][7] + bb[c0 + 7]);
        *(float4*)(ob + w * 64 + c0)     = o0;
        *(float4*)(ob + w * 64 + c0 + 4) = o1;
    }
}

// ---------------- launch ----------------
extern "C" void kernel_launch(void* const* d_in, const int* in_sizes, int n_in,
                              void* d_out, int out_size) {
    const float* x  = (const float*)d_in[0];
    const float* w0 = (const float*)d_in[1];
    const float* w1 = (const float*)d_in[2];
    const float* rw = (const float*)d_in[3];
    const float* rb = (const float*)d_in[4];
    float* out = (float*)d_out;

    const int SMEM_BIG = (64 * 260 + 64 * 68 + 64) * 4;   // 84224 bytes
    cudaFuncSetAttribute(k_s5, cudaFuncAttributeMaxDynamicSharedMemorySize, SMEM_BIG);

    k_init<<<64, 256>>>();
    k_a<<<512, 256>>>(x);
    dim3 gb(32, 8);
    k_b<<<gb, 256>>>();
    k_c<<<2048, 256>>>(w0, w1);
    dim3 g4(16, 4, 8);
    k_s4<<<g4, 256>>>();
    k_s5<<<2048, 256, SMEM_BIG>>>(x, rw, rb, out);
}

// round 11
// speedup vs baseline: 1.3681x; 1.0546x over previous
#include <cuda_runtime.h>
#include <math.h>

// Problem constants: N=8, R=256, IN=64, OUT=64, MODE=32
// kx mode list (64): k<32 -> kx=k ; k>=32 -> kx=192+k

// ---------------- device scratch ----------------
__device__ float g_T2aT[256 * 64];    // fwd w-DFT, transposed: [w][r=p*32+ky]
__device__ float g_T1T[256 * 128];    // fwd h-DFT cos/sin, transposed: [h][m] m<64:cos m>=64:sin
__device__ float g_T4T[128 * 512];    // inv h-DFT, transposed: [kxp][hp]
__device__ float g_T5t[64 * 256];     // inv w-DFT, transposed: [kyp][w]
__device__ float g_Xw[(size_t)8 * 256 * 4096];  // [n][h][p*2048+ky*64+i]  (33.5MB)
__device__ float g_C [(size_t)8 * 128 * 4096];  // [n][m(cos|sin)][p*2048+ky*64+i] (16.8MB)
__device__ float g_F [(size_t)8 * 128 * 32 * 64]; // [n][kxp][ky][o] (8.4MB)
__device__ float g_G [(size_t)8 * 512 * 2048];    // [n][hp][ky*64+o] (33.5MB)

__device__ __forceinline__ float silu_f(float t) {
    return t / (1.0f + __expf(-t));
}

// ---------------- twiddle init ----------------
__global__ void k_init() {
    int t = blockIdx.x * blockDim.x + threadIdx.x;   // 16384 threads
    {
        int w = t >> 6, r = t & 63;
        int p = r >> 5, ky = r & 31;
        float s, c;
        sincospif((float)((ky * w) & 255) * (1.0f / 128.0f), &s, &c);
        g_T2aT[w * 64 + r] = p ? -s : c;
    }
    {
        int h = t >> 6, k = t & 63;
        int kx = (k < 32) ? k : 192 + k;
        float s, c;
        sincospif((float)((kx * h) & 255) * (1.0f / 128.0f), &s, &c);
        g_T1T[h * 128 + k]      = c;
        g_T1T[h * 128 + 64 + k] = s;
    }
    {
        int h = t >> 6, k = t & 63;
        int kx = (k < 32) ? k : 192 + k;
        float s, c;
        sincospif((float)((kx * h) & 255) * (1.0f / 128.0f), &s, &c);
        g_T4T[(2 * k)     * 512 + 2 * h]     = c;
        g_T4T[(2 * k + 1) * 512 + 2 * h]     = -s;
        g_T4T[(2 * k)     * 512 + 2 * h + 1] = s;
        g_T4T[(2 * k + 1) * 512 + 2 * h + 1] = c;
    }
    {
        int r = t >> 8, w = t & 255;
        int ky = r >> 1, p = r & 1;
        float s, c;
        sincospif((float)((ky * w) & 255) * (1.0f / 128.0f), &s, &c);
        float f = (ky == 0) ? 1.0f : 2.0f;
        g_T5t[r * 256 + w] = p ? -f * s : f * c;
    }
}

// ---------------- Stage A: w-DFT first (double-buffered) ----------------
__global__ void __launch_bounds__(256, 2) k_a(const float* __restrict__ x) {
    __shared__ float As[2][16][68];    // [k][r]
    __shared__ float Bs[2][16][256];   // [k][(hl,i)]
    int tid = threadIdx.x;
    int n = blockIdx.x >> 6;
    int h0 = (blockIdx.x & 63) * 4;
    const float* B = x + (size_t)n * 4194304 + (size_t)h0 * 16384;
    float acc[8][8] = {};
    int r0 = (tid >> 5) * 8, c0 = (tid & 31) * 8;
    int ka = tid >> 4, ra4 = tid & 15;

    float4 pa;
    float4 pb[4];
    pa = *(const float4*)(g_T2aT + ka * 64 + ra4 * 4);
#pragma unroll
    for (int q = 0; q < 4; q++) {
        int e = tid + q * 256;
        int kk = e >> 6, c4 = e & 63;
        int hl = c4 >> 4, i4 = c4 & 15;
        pb[q] = *(const float4*)(B + hl * 16384 + kk * 64 + i4 * 4);
    }
    *(float4*)&As[0][ka][ra4 * 4] = pa;
#pragma unroll
    for (int q = 0; q < 4; q++) {
        int e = tid + q * 256;
        int kk = e >> 6, c4 = e & 63;
        *(float4*)&Bs[0][kk][c4 * 4] = pb[q];
    }
    __syncthreads();
    int buf = 0;
    for (int kc = 0; kc < 256; kc += 16) {
        if (kc + 16 < 256) {
            pa = *(const float4*)(g_T2aT + (kc + 16 + ka) * 64 + ra4 * 4);
#pragma unroll
            for (int q = 0; q < 4; q++) {
                int e = tid + q * 256;
                int kk = e >> 6, c4 = e & 63;
                int hl = c4 >> 4, i4 = c4 & 15;
                pb[q] = *(const float4*)(B + hl * 16384 + (kc + 16 + kk) * 64 + i4 * 4);
            }
        }
#pragma unroll
        for (int k = 0; k < 16; k++) {
            float a[8], b[8];
            *(float4*)(a)     = *(float4*)&As[buf][k][r0];
            *(float4*)(a + 4) = *(float4*)&As[buf][k][r0 + 4];
            *(float4*)(b)     = *(float4*)&Bs[buf][k][c0];
            *(float4*)(b + 4) = *(float4*)&Bs[buf][k][c0 + 4];
#pragma unroll
            for (int i = 0; i < 8; i++)
#pragma unroll
                for (int j = 0; j < 8; j++) acc[i][j] += a[i] * b[j];
        }
        if (kc + 16 < 256) {
            *(float4*)&As[buf ^ 1][ka][ra4 * 4] = pa;
#pragma unroll
            for (int q = 0; q < 4; q++) {
                int e = tid + q * 256;
                int kk = e >> 6, c4 = e & 63;
                *(float4*)&Bs[buf ^ 1][kk][c4 * 4] = pb[q];
            }
        }
        __syncthreads();
        buf ^= 1;
    }
    int hl = c0 >> 6, i = c0 & 63;
    int p0 = r0 >> 5;
    float* O = g_Xw + (size_t)n * 1048576 + (size_t)(h0 + hl) * 4096 + (size_t)p0 * 2048 + i;
#pragma unroll
    for (int r = 0; r < 8; r++) {
        int ky = (r0 + r) & 31;
        *(float4*)(O + ky * 64)     = make_float4(acc[r][0], acc[r][1], acc[r][2], acc[r][3]);
        *(float4*)(O + ky * 64 + 4) = make_float4(acc[r][4], acc[r][5], acc[r][6], acc[r][7]);
    }
}

// ---------------- Stage B: h-DFT (cos & sin planes), double-buffered ----------------
__global__ void __launch_bounds__(256, 2) k_b() {
    __shared__ float As[2][16][132];
    __shared__ float Bs[2][16][128];
    int tid = threadIdx.x;
    int n = blockIdx.y;
    int colbase = blockIdx.x * 128;
    const float* B = g_Xw + (size_t)n * 1048576;
    float acc[8][8] = {};
    int r0 = (tid >> 4) * 8, c0 = (tid & 15) * 8;

    float4 pa[2], pb[2];
#pragma unroll
    for (int q = 0; q < 2; q++) {
        int e = tid + q * 256;
        int kk = e >> 5, m4 = e & 31;
        pa[q] = *(const float4*)(g_T1T + kk * 128 + m4 * 4);
        pb[q] = *(const float4*)(B + (size_t)kk * 4096 + colbase + m4 * 4);
    }
#pragma unroll
    for (int q = 0; q < 2; q++) {
        int e = tid + q * 256;
        int kk = e >> 5, m4 = e & 31;
        *(float4*)&As[0][kk][m4 * 4] = pa[q];
        *(float4*)&Bs[0][kk][m4 * 4] = pb[q];
    }
    __syncthreads();
    int buf = 0;
    for (int kc = 0; kc < 256; kc += 16) {
        if (kc + 16 < 256) {
#pragma unroll
            for (int q = 0; q < 2; q++) {
                int e = tid + q * 256;
                int kk = e >> 5, m4 = e & 31;
                pa[q] = *(const float4*)(g_T1T + (kc + 16 + kk) * 128 + m4 * 4);
                pb[q] = *(const float4*)(B + (size_t)(kc + 16 + kk) * 4096 + colbase + m4 * 4);
            }
        }
#pragma unroll
        for (int k = 0; k < 16; k++) {
            float a[8], b[8];
            *(float4*)(a)     = *(float4*)&As[buf][k][r0];
            *(float4*)(a + 4) = *(float4*)&As[buf][k][r0 + 4];
            *(float4*)(b)     = *(float4*)&Bs[buf][k][c0];
            *(float4*)(b + 4) = *(float4*)&Bs[buf][k][c0 + 4];
#pragma unroll
            for (int i = 0; i < 8; i++)
#pragma unroll
                for (int j = 0; j < 8; j++) acc[i][j] += a[i] * b[j];
        }
        if (kc + 16 < 256) {
#pragma unroll
            for (int q = 0; q < 2; q++) {
                int e = tid + q * 256;
                int kk = e >> 5, m4 = e & 31;
                *(float4*)&As[buf ^ 1][kk][m4 * 4] = pa[q];
                *(float4*)&Bs[buf ^ 1][kk][m4 * 4] = pb[q];
            }
        }
        __syncthreads();
        buf ^= 1;
    }
    float* C = g_C + (size_t)n * 524288 + colbase;
#pragma unroll
    for (int i = 0; i < 8; i++) {
        int row = r0 + i;
        *(float4*)(C + (size_t)row * 4096 + c0)     = make_float4(acc[i][0], acc[i][1], acc[i][2], acc[i][3]);
        *(float4*)(C + (size_t)row * 4096 + c0 + 4) = make_float4(acc[i][4], acc[i][5], acc[i][6], acc[i][7]);
    }
}

// ---------------- S3: complex recombine + mode channel mix, scale 1/65536 ----------------
__global__ void __launch_bounds__(256) k_c(const float* __restrict__ w0,
                                           const float* __restrict__ w1) {
    __shared__ float Wre[64][64], Wim[64][64];
    __shared__ float Xre[8][64], Xim[8][64];
    int tid = threadIdx.x;
    int ky = blockIdx.x & 31, k = blockIdx.x >> 5;
    const float* W = (k < 32) ? (w0 + (size_t)(k * 32 + ky) * 4096 * 2)
                              : (w1 + (size_t)((k - 32) * 32 + ky) * 4096 * 2);
#pragma unroll
    for (int q = 0; q < 16; q++) {
        int e = tid + q * 256;          // i*64+o
        float2 v = *(const float2*)(W + (size_t)e * 2);
        Wre[e >> 6][e & 63] = v.x;
        Wim[e >> 6][e & 63] = v.y;
    }
#pragma unroll
    for (int q = 0; q < 2; q++) {
        int e = tid + q * 256;          // n*64+i
        int n = e >> 6, i = e & 63;
        const float* Cn = g_C + (size_t)n * 524288;
        float cc0 = Cn[(size_t)k * 4096 + ky * 64 + i];
        float cc1 = Cn[(size_t)k * 4096 + 2048 + ky * 64 + i];
        float cs0 = Cn[(size_t)(64 + k) * 4096 + ky * 64 + i];
        float cs1 = Cn[(size_t)(64 + k) * 4096 + 2048 + ky * 64 + i];
        Xre[n][i] = cc0 + cs1;
        Xim[n][i] = cc1 - cs0;
    }
    __syncthreads();
    const float sc = 1.0f / 65536.0f;
#pragma unroll
    for (int q = 0; q < 2; q++) {
        int e = tid + q * 256;
        int n = e >> 6, o = e & 63;
        float fre = 0.0f, fim = 0.0f;
#pragma unroll 8
        for (int i = 0; i < 64; i++) {
            float xr = Xre[n][i], xi = Xim[n][i];
            float wr = Wre[i][o], wi = Wim[i][o];
            fre += xr * wr - xi * wi;
            fim += xr * wi + xi * wr;
        }
        g_F[((size_t)(n * 128 + 2 * k) * 32 + ky) * 64 + o]     = fre * sc;
        g_F[((size_t)(n * 128 + 2 * k + 1) * 32 + ky) * 64 + o] = fim * sc;
    }
}

// ---------------- S4: per n: G[512 hp][2048] = T4[512][128] @ F[n], double-buffered ----------------
__global__ void __launch_bounds__(256, 2) k_s4() {
    __shared__ float As[2][16][132];
    __shared__ float Bs[2][16][128];
    int tid = threadIdx.x;
    int colbase = blockIdx.x * 128;
    int m0 = blockIdx.y * 128;
    int n = blockIdx.z;
    const float* B = g_F + (size_t)n * 128 * 2048;
    float acc[8][8] = {};
    int r0 = (tid >> 4) * 8, c0 = (tid & 15) * 8;

    float4 pa[2], pb[2];
#pragma unroll
    for (int q = 0; q < 2; q++) {
        int e = tid + q * 256;
        int kk = e >> 5, m4 = e & 31;
        pa[q] = *(const float4*)(g_T4T + (size_t)kk * 512 + m0 + m4 * 4);
        pb[q] = *(const float4*)(B + (size_t)kk * 2048 + colbase + m4 * 4);
    }
#pragma unroll
    for (int q = 0; q < 2; q++) {
        int e = tid + q * 256;
        int kk = e >> 5, m4 = e & 31;
        *(float4*)&As[0][kk][m4 * 4] = pa[q];
        *(float4*)&Bs[0][kk][m4 * 4] = pb[q];
    }
    __syncthreads();
    int buf = 0;
    for (int kc = 0; kc < 128; kc += 16) {
        if (kc + 16 < 128) {
#pragma unroll
            for (int q = 0; q < 2; q++) {
                int e = tid + q * 256;
                int kk = e >> 5, m4 = e & 31;
                pa[q] = *(const float4*)(g_T4T + (size_t)(kc + 16 + kk) * 512 + m0 + m4 * 4);
                pb[q] = *(const float4*)(B + (size_t)(kc + 16 + kk) * 2048 + colbase + m4 * 4);
            }
        }
#pragma unroll
        for (int k = 0; k < 16; k++) {
            float a[8], b[8];
            *(float4*)(a)     = *(float4*)&As[buf][k][r0];
            *(float4*)(a + 4) = *(float4*)&As[buf][k][r0 + 4];
            *(float4*)(b)     = *(float4*)&Bs[buf][k][c0];
            *(float4*)(b + 4) = *(float4*)&Bs[buf][k][c0 + 4];
#pragma unroll
            for (int i = 0; i < 8; i++)
#pragma unroll
                for (int j = 0; j < 8; j++) acc[i][j] += a[i] * b[j];
        }
        if (kc + 16 < 128) {
#pragma unroll
            for (int q = 0; q < 2; q++) {
                int e = tid + q * 256;
                int kk = e >> 5, m4 = e & 31;
                *(float4*)&As[buf ^ 1][kk][m4 * 4] = pa[q];
                *(float4*)&Bs[buf ^ 1][kk][m4 * 4] = pb[q];
            }
        }
        __syncthreads();
        buf ^= 1;
    }
    float* C = g_G + (size_t)n * 512 * 2048 + colbase;
#pragma unroll
    for (int i = 0; i < 8; i++) {
        int row = m0 + r0 + i;
        *(float4*)(C + (size_t)row * 2048 + c0)     = make_float4(acc[i][0], acc[i][1], acc[i][2], acc[i][3]);
        *(float4*)(C + (size_t)row * 2048 + c0 + 4) = make_float4(acc[i][4], acc[i][5], acc[i][6], acc[i][7]);
    }
}

// ---------------- S5 (fused with residual), split into w-halves for occupancy:
//   per (n,h,wh): y[w][o] = T5t^T @ G + x[n,h]^T @ res_w + res_b, silu ----------------
__global__ void __launch_bounds__(256) k_s5(const float* __restrict__ x,
                                            const float* __restrict__ rw,
                                            const float* __restrict__ rb,
                                            float* __restrict__ out) {
    extern __shared__ float sm[];
    float(*As)[132] = (float(*)[132])sm;              // [64 k][128 w(+pad)]
    float(*Bs)[68]  = (float(*)[68])(sm + 64 * 132);  // [64 k][64 o(+pad)]
    float* bb = sm + 64 * 132 + 64 * 68;
    int tid = threadIdx.x;
    int wh = blockIdx.x & 1;
    int h  = (blockIdx.x >> 1) & 255;
    int n  = blockIdx.x >> 9;
    int w0base = wh * 128;
    int r0 = (tid >> 4) * 8, c0 = (tid & 15) * 4;
    float acc[8][4] = {};

    // ----- pass 1: spectral  As = T5t[k][w-half], Bs = G[kyp][o] -----
#pragma unroll
    for (int q = 0; q < 8; q++) {
        int e = tid + q * 256;           // 2048 f4 : 64 k x 32 w4
        int k = e >> 5, w4 = e & 31;
        *(float4*)&As[k][w4 * 4] = *(const float4*)(g_T5t + k * 256 + w0base + w4 * 4);
    }
    const float* G = g_G + (size_t)(n * 256 + h) * 4096;  // [p][ky][o]
#pragma unroll
    for (int q = 0; q < 4; q++) {
        int e4 = tid + q * 256;          // 1024 f4
        int p = e4 >> 9, ky = (e4 >> 4) & 31, j = e4 & 15;
        float4 v = *(const float4*)(G + p * 2048 + ky * 64 + j * 4);
        *(float4*)&Bs[2 * ky + p][j * 4] = v;
    }
    if (tid < 64) bb[tid] = rb[tid];
    __syncthreads();
#pragma unroll 8
    for (int k = 0; k < 64; k++) {
        float a[8], b[4];
        *(float4*)(a)     = *(float4*)&As[k][r0];
        *(float4*)(a + 4) = *(float4*)&As[k][r0 + 4];
        *(float4*)(b)     = *(float4*)&Bs[k][c0];
#pragma unroll
        for (int i = 0; i < 8; i++)
#pragma unroll
            for (int j = 0; j < 4; j++) acc[i][j] += a[i] * b[j];
    }
    __syncthreads();

    // ----- pass 2: residual  As = x[n,h]^T [i][w-half], Bs = rw [i][o] -----
    const float* xb = x + (size_t)(n * 256 + h) * 16384 + (size_t)w0base * 64;  // [w][i]
#pragma unroll
    for (int q = 0; q < 8; q++) {
        int f4 = tid + q * 256;          // 2048 f4 : 128 w x 16 i4
        int w = f4 >> 4, j = f4 & 15;
        float4 v = *(const float4*)(xb + w * 64 + j * 4);
        As[j * 4 + 0][w] = v.x; As[j * 4 + 1][w] = v.y;
        As[j * 4 + 2][w] = v.z; As[j * 4 + 3][w] = v.w;
    }
#pragma unroll
    for (int q = 0; q < 4; q++) {
        int f4 = tid + q * 256;          // 1024 f4 : 64 k x 16 j
        int k = f4 >> 4, j = f4 & 15;
        *(float4*)&Bs[k][j * 4] = *(const float4*)(rw + k * 64 + j * 4);
    }
    __syncthreads();
#pragma unroll 8
    for (int k = 0; k < 64; k++) {
        float a[8], b[4];
        *(float4*)(a)     = *(float4*)&As[k][r0];
        *(float4*)(a + 4) = *(float4*)&As[k][r0 + 4];
        *(float4*)(b)     = *(float4*)&Bs[k][c0];
#pragma unroll
        for (int i = 0; i < 8; i++)
#pragma unroll
            for (int j = 0; j < 4; j++) acc[i][j] += a[i] * b[j];
    }

    float* ob = out + (size_t)(n * 256 + h) * 16384 + (size_t)w0base * 64;   // [w][o]
#pragma unroll
    for (int i = 0; i < 8; i++) {
        int w = r0 + i;
        float4 o0;
        o0.x = silu_f(acc[i][0] + bb[c0 + 0]);
        o0.y = silu_f(acc[i][1] + bb[c0 + 1]);
        o0.z = silu_f(acc[i][2] + bb[c0 + 2]);
        o0.w = silu_f(acc[i][3] + bb[c0 + 3]);
        *(float4*)(ob + w * 64 + c0) = o0;
    }
}

// ---------------- launch ----------------
extern "C" void kernel_launch(void* const* d_in, const int* in_sizes, int n_in,
                              void* d_out, int out_size) {
    const float* x  = (const float*)d_in[0];
    const float* w0 = (const float*)d_in[1];
    const float* w1 = (const float*)d_in[2];
    const float* rw = (const float*)d_in[3];
    const float* rb = (const float*)d_in[4];
    float* out = (float*)d_out;

    const int SMEM_S5 = (64 * 132 + 64 * 68 + 64) * 4;   // 51456 bytes
    cudaFuncSetAttribute(k_s5, cudaFuncAttributeMaxDynamicSharedMemorySize, SMEM_S5);

    k_init<<<64, 256>>>();
    k_a<<<512, 256>>>(x);
    dim3 gb(32, 8);
    k_b<<<gb, 256>>>();
    k_c<<<2048, 256>>>(w0, w1);
    dim3 g4(16, 4, 8);
    k_s4<<<g4, 256>>>();
    k_s5<<<4096, 256, SMEM_S5>>>(x, rw, rb, out);   // 8 n * 256 h * 2 w-halves
}

// round 12
// speedup vs baseline: 1.4525x; 1.0617x over previous
#include <cuda_runtime.h>
#include <math.h>

// Problem constants: N=8, R=256, IN=64, OUT=64, MODE=32
// kx mode list (64): k<32 -> kx=k ; k>=32 -> kx=192+k

// ---------------- device scratch ----------------
__device__ float g_TA[128 * 64];      // fwd w-DFT folded: [w][r]  r<32: cos(2pi ky w/256), r>=32: -sin
__device__ float g_TB[128 * 128];     // fwd h-DFT folded: [h][c]  c<64: cos(2pi kx h/256), c>=64: +sin
__device__ float g_T4T[128 * 512];    // inv h-DFT, transposed: [kxp][hp]
__device__ float g_T5t[64 * 256];     // inv w-DFT, transposed: [kyp][w]
__device__ float g_Xw[(size_t)8 * 256 * 4096];  // [n][h][p*2048+ky*64+i]  (33.5MB)
__device__ float g_C [(size_t)8 * 128 * 4096];  // [n][m(cos|sin)][p*2048+ky*64+i] (16.8MB)
__device__ float g_F [(size_t)8 * 128 * 32 * 64]; // [n][kxp][ky][o] (8.4MB)
__device__ float g_G [(size_t)8 * 512 * 2048];    // [n][hp][ky*64+o] (33.5MB)

__device__ __forceinline__ float silu_f(float t) {
    return t / (1.0f + __expf(-t));
}

// ---------------- twiddle init ----------------
__global__ void k_init() {
    int t = blockIdx.x * blockDim.x + threadIdx.x;   // 16384 threads
    if (t < 8192) {
        // g_TA[w][r]: r<32: cos(2pi ky w/256); r>=32: -sin
        int w = t >> 6, rr = t & 63;
        int ty = rr >> 5, ky = rr & 31;
        float s, c;
        sincospif((float)((ky * w) & 255) * (1.0f / 128.0f), &s, &c);
        g_TA[w * 64 + rr] = ty ? -s : c;
    }
    {
        // g_TB[h][c]: c<64: cos(2pi kx h/256); c>=64: +sin
        int h = t >> 7, cc = t & 127;
        int ty = cc >> 6, k = cc & 63;
        int kx = (k < 32) ? k : 192 + k;
        float s, c;
        sincospif((float)((kx * h) & 255) * (1.0f / 128.0f), &s, &c);
        g_TB[h * 128 + cc] = ty ? s : c;
    }
    {
        // T4T[kxp][hp]: inverse e^{+i2pi kx h/256}
        int h = t >> 6, k = t & 63;
        int kx = (k < 32) ? k : 192 + k;
        float s, c;
        sincospif((float)((kx * h) & 255) * (1.0f / 128.0f), &s, &c);
        g_T4T[(2 * k)     * 512 + 2 * h]     = c;
        g_T4T[(2 * k + 1) * 512 + 2 * h]     = -s;
        g_T4T[(2 * k)     * 512 + 2 * h + 1] = s;
        g_T4T[(2 * k + 1) * 512 + 2 * h + 1] = c;
    }
    {
        // T5t[kyp][w]: y[w] = sum_ky c_ky*(Gre*cos - Gim*sin), c_0=1 else 2
        int r = t >> 8, w = t & 255;
        int ky = r >> 1, p = r & 1;
        float s, c;
        sincospif((float)((ky * w) & 255) * (1.0f / 128.0f), &s, &c);
        float f = (ky == 0) ? 1.0f : 2.0f;
        g_T5t[r * 256 + w] = p ? -f * s : f * c;
    }
}

// ---------------- Stage A (folded): per (n, 8h, type t):
//   t=0: Xw[ky] = E-GEMM (K=128) + (-1)^ky x[128];  t=1: Xw[32+ky] = O-GEMM ----------------
__global__ void __launch_bounds__(256) k_a(const float* __restrict__ x) {
    __shared__ float As[16][36];     // [kk][32 r]
    __shared__ float Bs[16][512];    // [kk][8h x 64i]
    __shared__ float xs[512];        // x[*, w=128, *] for correction (t=0)
    int tid = threadIdx.x;
    int hg = blockIdx.x, t = blockIdx.y, n = blockIdx.z;
    int h0 = hg * 8;
    const float* xb = x + (size_t)n * 4194304 + (size_t)h0 * 16384;
    if (tid < 128) {
        int hl = tid >> 4, i4 = tid & 15;
        *(float4*)&xs[hl * 64 + i4 * 4] = *(const float4*)(xb + hl * 16384 + 128 * 64 + i4 * 4);
    }
    float acc[4][16] = {};
    int r0 = (tid >> 5) * 4;
    int cg0 = (tid & 31) * 4;        // 4 strided f4 col groups: cg0 + g*128

    for (int kc = 0; kc < 128; kc += 16) {
        if (tid < 128) {
            int kk = tid >> 3, r4 = tid & 7;
            *(float4*)&As[kk][r4 * 4] = *(const float4*)(g_TA + (kc + kk) * 64 + t * 32 + r4 * 4);
        }
#pragma unroll
        for (int q = 0; q < 8; q++) {
            int e = tid + q * 256;
            int kk = e >> 7, c4 = e & 127;
            int hl = c4 >> 4, i4 = c4 & 15;
            int w = kc + kk;
            int m = (256 - w) & 255;
            const float* base = xb + hl * 16384;
            float4 vw = *(const float4*)(base + (size_t)w * 64 + i4 * 4);
            float4 vm = *(const float4*)(base + (size_t)m * 64 + i4 * 4);
            float4 v;
            if (t == 0) {
                v = w ? make_float4(vw.x + vm.x, vw.y + vm.y, vw.z + vm.z, vw.w + vm.w) : vw;
            } else {
                v = w ? make_float4(vw.x - vm.x, vw.y - vm.y, vw.z - vm.z, vw.w - vm.w)
                      : make_float4(0.f, 0.f, 0.f, 0.f);
            }
            *(float4*)&Bs[kk][c4 * 4] = v;
        }
        __syncthreads();
#pragma unroll
        for (int k = 0; k < 16; k++) {
            float a[4], b[16];
            *(float4*)a = *(float4*)&As[k][r0];
#pragma unroll
            for (int g = 0; g < 4; g++)
                *(float4*)(b + g * 4) = *(float4*)&Bs[k][cg0 + g * 128];
#pragma unroll
            for (int i = 0; i < 4; i++)
#pragma unroll
                for (int j = 0; j < 16; j++) acc[i][j] += a[i] * b[j];
        }
        __syncthreads();
    }
    // correction: += (-1)^ky * x[128]  (cos rows only)
    if (t == 0) {
#pragma unroll
        for (int r = 0; r < 4; r++) {
            float sign = ((r0 + r) & 1) ? -1.0f : 1.0f;
#pragma unroll
            for (int g = 0; g < 4; g++) {
                int cg = cg0 + g * 128;
#pragma unroll
                for (int j = 0; j < 4; j++) acc[r][g * 4 + j] += sign * xs[cg + j];
            }
        }
    }
    // store: Xw[n][h0+hl][t*2048 + ky*64 + i]
#pragma unroll
    for (int r = 0; r < 4; r++) {
        int ky = r0 + r;
#pragma unroll
        for (int g = 0; g < 4; g++) {
            int cg = cg0 + g * 128;
            int hl = cg >> 6, ib = cg & 63;
            float* O = g_Xw + (size_t)n * 1048576 + (size_t)(h0 + hl) * 4096 + t * 2048 + ky * 64 + ib;
            *(float4*)O = make_float4(acc[r][g * 4 + 0], acc[r][g * 4 + 1],
                                      acc[r][g * 4 + 2], acc[r][g * 4 + 3]);
        }
    }
}

// ---------------- Stage B (folded): per (colblock, n, type t):
//   t=0: C[k] = E-GEMM over h (K=128) + (-1)^k Xw[128];  t=1: C[64+k] = O-GEMM ----------------
__global__ void __launch_bounds__(256, 2) k_b() {
    __shared__ float As[2][16][68];   // [kk][64 k]
    __shared__ float Bs[2][16][128];
    __shared__ float xs[128];         // Xw[n][128][cols] for correction
    int tid = threadIdx.x;
    int cb = blockIdx.x * 128;
    int n = blockIdx.y, t = blockIdx.z;
    const float* B = g_Xw + (size_t)n * 1048576;
    if (tid < 32)
        *(float4*)&xs[tid * 4] = *(const float4*)(B + (size_t)128 * 4096 + cb + tid * 4);
    float acc[8][4] = {};
    int r0 = (tid >> 5) * 8, c0 = (tid & 31) * 4;
    int ka = tid >> 4, ra4 = tid & 15;   // A: 256 f4/chunk

    float4 pa;
    float4 ph[2], pm[2];
    // prologue chunk 0
    pa = *(const float4*)(g_TB + ka * 128 + t * 64 + ra4 * 4);
#pragma unroll
    for (int q = 0; q < 2; q++) {
        int e = tid + q * 256;
        int kk = e >> 5, c4 = e & 31;
        int m = (256 - kk) & 255;
        ph[q] = *(const float4*)(B + (size_t)kk * 4096 + cb + c4 * 4);
        pm[q] = *(const float4*)(B + (size_t)m * 4096 + cb + c4 * 4);
    }
    {
        *(float4*)&As[0][ka][ra4 * 4] = pa;
#pragma unroll
        for (int q = 0; q < 2; q++) {
            int e = tid + q * 256;
            int kk = e >> 5, c4 = e & 31;
            float4 v;
            if (t == 0)
                v = kk ? make_float4(ph[q].x + pm[q].x, ph[q].y + pm[q].y,
                                     ph[q].z + pm[q].z, ph[q].w + pm[q].w) : ph[q];
            else
                v = kk ? make_float4(ph[q].x - pm[q].x, ph[q].y - pm[q].y,
                                     ph[q].z - pm[q].z, ph[q].w - pm[q].w)
                       : make_float4(0.f, 0.f, 0.f, 0.f);
            *(float4*)&Bs[0][kk][c4 * 4] = v;
        }
    }
    __syncthreads();
    int buf = 0;
    for (int kc = 0; kc < 128; kc += 16) {
        if (kc + 16 < 128) {
            pa = *(const float4*)(g_TB + (kc + 16 + ka) * 128 + t * 64 + ra4 * 4);
#pragma unroll
            for (int q = 0; q < 2; q++) {
                int e = tid + q * 256;
                int kk = e >> 5, c4 = e & 31;
                int h = kc + 16 + kk;
                int m = (256 - h) & 255;
                ph[q] = *(const float4*)(B + (size_t)h * 4096 + cb + c4 * 4);
                pm[q] = *(const float4*)(B + (size_t)m * 4096 + cb + c4 * 4);
            }
        }
#pragma unroll
        for (int k = 0; k < 16; k++) {
            float a[8], b[4];
            *(float4*)(a)     = *(float4*)&As[buf][k][r0];
            *(float4*)(a + 4) = *(float4*)&As[buf][k][r0 + 4];
            *(float4*)(b)     = *(float4*)&Bs[buf][k][c0];
#pragma unroll
            for (int i = 0; i < 8; i++)
#pragma unroll
                for (int j = 0; j < 4; j++) acc[i][j] += a[i] * b[j];
        }
        if (kc + 16 < 128) {
            *(float4*)&As[buf ^ 1][ka][ra4 * 4] = pa;
#pragma unroll
            for (int q = 0; q < 2; q++) {
                int e = tid + q * 256;
                int kk = e >> 5, c4 = e & 31;
                int h = kc + 16 + kk;
                float4 v;
                if (t == 0)
                    v = make_float4(ph[q].x + pm[q].x, ph[q].y + pm[q].y,
                                    ph[q].z + pm[q].z, ph[q].w + pm[q].w);
                else
                    v = make_float4(ph[q].x - pm[q].x, ph[q].y - pm[q].y,
                                    ph[q].z - pm[q].z, ph[q].w - pm[q].w);
                (void)h;
                *(float4*)&Bs[buf ^ 1][kk][c4 * 4] = v;
            }
        }
        __syncthreads();
        buf ^= 1;
    }
    // correction: cos rows get (-1)^k * Xw[128]
    if (t == 0) {
#pragma unroll
        for (int r = 0; r < 8; r++) {
            float sign = ((r0 + r) & 1) ? -1.0f : 1.0f;
#pragma unroll
            for (int j = 0; j < 4; j++) acc[r][j] += sign * xs[c0 + j];
        }
    }
    float* C = g_C + (size_t)n * 524288 + (size_t)(t * 64) * 4096 + cb;
#pragma unroll
    for (int i = 0; i < 8; i++) {
        int row = r0 + i;
        *(float4*)(C + (size_t)row * 4096 + c0) =
            make_float4(acc[i][0], acc[i][1], acc[i][2], acc[i][3]);
    }
}

// ---------------- S3: complex recombine + mode channel mix, scale 1/65536 ----------------
__global__ void __launch_bounds__(256) k_c(const float* __restrict__ w0,
                                           const float* __restrict__ w1) {
    __shared__ float Wre[64][64], Wim[64][64];
    __shared__ float Xre[8][64], Xim[8][64];
    int tid = threadIdx.x;
    int ky = blockIdx.x & 31, k = blockIdx.x >> 5;
    const float* W = (k < 32) ? (w0 + (size_t)(k * 32 + ky) * 4096 * 2)
                              : (w1 + (size_t)((k - 32) * 32 + ky) * 4096 * 2);
#pragma unroll
    for (int q = 0; q < 16; q++) {
        int e = tid + q * 256;          // i*64+o
        float2 v = *(const float2*)(W + (size_t)e * 2);
        Wre[e >> 6][e & 63] = v.x;
        Wim[e >> 6][e & 63] = v.y;
    }
#pragma unroll
    for (int q = 0; q < 2; q++) {
        int e = tid + q * 256;          // n*64+i
        int n = e >> 6, i = e & 63;
        const float* Cn = g_C + (size_t)n * 524288;
        float cc0 = Cn[(size_t)k * 4096 + ky * 64 + i];
        float cc1 = Cn[(size_t)k * 4096 + 2048 + ky * 64 + i];
        float cs0 = Cn[(size_t)(64 + k) * 4096 + ky * 64 + i];
        float cs1 = Cn[(size_t)(64 + k) * 4096 + 2048 + ky * 64 + i];
        Xre[n][i] = cc0 + cs1;
        Xim[n][i] = cc1 - cs0;
    }
    __syncthreads();
    const float sc = 1.0f / 65536.0f;
#pragma unroll
    for (int q = 0; q < 2; q++) {
        int e = tid + q * 256;
        int n = e >> 6, o = e & 63;
        float fre = 0.0f, fim = 0.0f;
#pragma unroll 8
        for (int i = 0; i < 64; i++) {
            float xr = Xre[n][i], xi = Xim[n][i];
            float wr = Wre[i][o], wi = Wim[i][o];
            fre += xr * wr - xi * wi;
            fim += xr * wi + xi * wr;
        }
        g_F[((size_t)(n * 128 + 2 * k) * 32 + ky) * 64 + o]     = fre * sc;
        g_F[((size_t)(n * 128 + 2 * k + 1) * 32 + ky) * 64 + o] = fim * sc;
    }
}

// ---------------- S4: per n: G[512 hp][2048] = T4[512][128] @ F[n], double-buffered ----------------
__global__ void __launch_bounds__(256, 2) k_s4() {
    __shared__ float As[2][16][132];
    __shared__ float Bs[2][16][128];
    int tid = threadIdx.x;
    int colbase = blockIdx.x * 128;
    int m0 = blockIdx.y * 128;
    int n = blockIdx.z;
    const float* B = g_F + (size_t)n * 128 * 2048;
    float acc[8][8] = {};
    int r0 = (tid >> 4) * 8, c0 = (tid & 15) * 8;

    float4 pa[2], pb[2];
#pragma unroll
    for (int q = 0; q < 2; q++) {
        int e = tid + q * 256;
        int kk = e >> 5, m4 = e & 31;
        pa[q] = *(const float4*)(g_T4T + (size_t)kk * 512 + m0 + m4 * 4);
        pb[q] = *(const float4*)(B + (size_t)kk * 2048 + colbase + m4 * 4);
    }
#pragma unroll
    for (int q = 0; q < 2; q++) {
        int e = tid + q * 256;
        int kk = e >> 5, m4 = e & 31;
        *(float4*)&As[0][kk][m4 * 4] = pa[q];
        *(float4*)&Bs[0][kk][m4 * 4] = pb[q];
    }
    __syncthreads();
    int buf = 0;
    for (int kc = 0; kc < 128; kc += 16) {
        if (kc + 16 < 128) {
#pragma unroll
            for (int q = 0; q < 2; q++) {
                int e = tid + q * 256;
                int kk = e >> 5, m4 = e & 31;
                pa[q] = *(const float4*)(g_T4T + (size_t)(kc + 16 + kk) * 512 + m0 + m4 * 4);
                pb[q] = *(const float4*)(B + (size_t)(kc + 16 + kk) * 2048 + colbase + m4 * 4);
            }
        }
#pragma unroll
        for (int k = 0; k < 16; k++) {
            float a[8], b[8];
            *(float4*)(a)     = *(float4*)&As[buf][k][r0];
            *(float4*)(a + 4) = *(float4*)&As[buf][k][r0 + 4];
            *(float4*)(b)     = *(float4*)&Bs[buf][k][c0];
            *(float4*)(b + 4) = *(float4*)&Bs[buf][k][c0 + 4];
#pragma unroll
            for (int i = 0; i < 8; i++)
#pragma unroll
                for (int j = 0; j < 8; j++) acc[i][j] += a[i] * b[j];
        }
        if (kc + 16 < 128) {
#pragma unroll
            for (int q = 0; q < 2; q++) {
                int e = tid + q * 256;
                int kk = e >> 5, m4 = e & 31;
                *(float4*)&As[buf ^ 1][kk][m4 * 4] = pa[q];
                *(float4*)&Bs[buf ^ 1][kk][m4 * 4] = pb[q];
            }
        }
        __syncthreads();
        buf ^= 1;
    }
    float* C = g_G + (size_t)n * 512 * 2048 + colbase;
#pragma unroll
    for (int i = 0; i < 8; i++) {
        int row = m0 + r0 + i;
        *(float4*)(C + (size_t)row * 2048 + c0)     = make_float4(acc[i][0], acc[i][1], acc[i][2], acc[i][3]);
        *(float4*)(C + (size_t)row * 2048 + c0 + 4) = make_float4(acc[i][4], acc[i][5], acc[i][6], acc[i][7]);
    }
}

// ---------------- S5 (fused with residual), split into w-halves for occupancy ----------------
__global__ void __launch_bounds__(256) k_s5(const float* __restrict__ x,
                                            const float* __restrict__ rw,
                                            const float* __restrict__ rb,
                                            float* __restrict__ out) {
    extern __shared__ float sm[];
    float(*As)[132] = (float(*)[132])sm;              // [64 k][128 w(+pad)]
    float(*Bs)[68]  = (float(*)[68])(sm + 64 * 132);  // [64 k][64 o(+pad)]
    float* bb = sm + 64 * 132 + 64 * 68;
    int tid = threadIdx.x;
    int wh = blockIdx.x & 1;
    int h  = (blockIdx.x >> 1) & 255;
    int n  = blockIdx.x >> 9;
    int w0base = wh * 128;
    int r0 = (tid >> 4) * 8, c0 = (tid & 15) * 4;
    float acc[8][4] = {};

    // ----- pass 1: spectral  As = T5t[k][w-half], Bs = G[kyp][o] -----
#pragma unroll
    for (int q = 0; q < 8; q++) {
        int e = tid + q * 256;           // 2048 f4 : 64 k x 32 w4
        int k = e >> 5, w4 = e & 31;
        *(float4*)&As[k][w4 * 4] = *(const float4*)(g_T5t + k * 256 + w0base + w4 * 4);
    }
    const float* G = g_G + (size_t)(n * 256 + h) * 4096;  // [p][ky][o]
#pragma unroll
    for (int q = 0; q < 4; q++) {
        int e4 = tid + q * 256;          // 1024 f4
        int p = e4 >> 9, ky = (e4 >> 4) & 31, j = e4 & 15;
        float4 v = *(const float4*)(G + p * 2048 + ky * 64 + j * 4);
        *(float4*)&Bs[2 * ky + p][j * 4] = v;
    }
    if (tid < 64) bb[tid] = rb[tid];
    __syncthreads();
#pragma unroll 8
    for (int k = 0; k < 64; k++) {
        float a[8], b[4];
        *(float4*)(a)     = *(float4*)&As[k][r0];
        *(float4*)(a + 4) = *(float4*)&As[k][r0 + 4];
        *(float4*)(b)     = *(float4*)&Bs[k][c0];
#pragma unroll
        for (int i = 0; i < 8; i++)
#pragma unroll
            for (int j = 0; j < 4; j++) acc[i][j] += a[i] * b[j];
    }
    __syncthreads();

    // ----- pass 2: residual  As = x[n,h]^T [i][w-half], Bs = rw [i][o] -----
    const float* xb = x + (size_t)(n * 256 + h) * 16384 + (size_t)w0base * 64;  // [w][i]
#pragma unroll
    for (int q = 0; q < 8; q++) {
        int f4 = tid + q * 256;          // 2048 f4 : 128 w x 16 i4
        int w = f4 >> 4, j = f4 & 15;
        float4 v = *(const float4*)(xb + w * 64 + j * 4);
        As[j * 4 + 0][w] = v.x; As[j * 4 + 1][w] = v.y;
        As[j * 4 + 2][w] = v.z; As[j * 4 + 3][w] = v.w;
    }
#pragma unroll
    for (int q = 0; q < 4; q++) {
        int f4 = tid + q * 256;          // 1024 f4 : 64 k x 16 j
        int k = f4 >> 4, j = f4 & 15;
        *(float4*)&Bs[k][j * 4] = *(const float4*)(rw + k * 64 + j * 4);
    }
    __syncthreads();
#pragma unroll 8
    for (int k = 0; k < 64; k++) {
        float a[8], b[4];
        *(float4*)(a)     = *(float4*)&As[k][r0];
        *(float4*)(a + 4) = *(float4*)&As[k][r0 + 4];
        *(float4*)(b)     = *(float4*)&Bs[k][c0];
#pragma unroll
        for (int i = 0; i < 8; i++)
#pragma unroll
            for (int j = 0; j < 4; j++) acc[i][j] += a[i] * b[j];
    }

    float* ob = out + (size_t)(n * 256 + h) * 16384 + (size_t)w0base * 64;   // [w][o]
#pragma unroll
    for (int i = 0; i < 8; i++) {
        int w = r0 + i;
        float4 o0;
        o0.x = silu_f(acc[i][0] + bb[c0 + 0]);
        o0.y = silu_f(acc[i][1] + bb[c0 + 1]);
        o0.z = silu_f(acc[i][2] + bb[c0 + 2]);
        o0.w = silu_f(acc[i][3] + bb[c0 + 3]);
        *(float4*)(ob + w * 64 + c0) = o0;
    }
}

// ---------------- launch ----------------
extern "C" void kernel_launch(void* const* d_in, const int* in_sizes, int n_in,
                              void* d_out, int out_size) {
    const float* x  = (const float*)d_in[0];
    const float* w0 = (const float*)d_in[1];
    const float* w1 = (const float*)d_in[2];
    const float* rw = (const float*)d_in[3];
    const float* rb = (const float*)d_in[4];
    float* out = (float*)d_out;

    const int SMEM_S5 = (64 * 132 + 64 * 68 + 64) * 4;   // 51456 bytes
    cudaFuncSetAttribute(k_s5, cudaFuncAttributeMaxDynamicSharedMemorySize, SMEM_S5);

    k_init<<<64, 256>>>();
    dim3 ga(32, 2, 8);                 // hg, type, n
    k_a<<<ga, 256>>>(x);
    dim3 gb(32, 8, 2);                 // colblock, n, type
    k_b<<<gb, 256>>>();
    k_c<<<2048, 256>>>(w0, w1);
    dim3 g4(16, 4, 8);
    k_s4<<<g4, 256>>>();
    k_s5<<<4096, 256, SMEM_S5>>>(x, rw, rb, out);   // 8 n * 256 h * 2 w-halves
}